// round 2
// baseline (speedup 1.0000x reference)
#include <cuda_runtime.h>
#include <math.h>

#define B_   2
#define S_   2048
#define D_   1024
#define H_   8
#define FFN_ 4096
#define DK_  128
#define VD_  2048
#define DV_  256
#define NT_  (B_*S_)   // 4096 tokens

// ---------------- scratch (static device allocations; harness-safe) -------
__device__ float d_Xn   [B_*S_*D_];
__device__ float d_Q    [B_*H_*S_*DK_];
__device__ float d_K    [B_*H_*S_*DK_];
__device__ float d_Kt   [B_*H_*DK_*S_];
__device__ float d_V    [B_*H_*S_*DV_];
__device__ float d_G    [B_*S_*VD_];
__device__ float d_Y    [B_*H_*S_*DV_];
__device__ float d_gated[B_*S_*VD_];
__device__ float d_X2   [B_*S_*D_];
__device__ float d_h1   [(size_t)B_*S_*FFN_];
__device__ float d_Sc   [(size_t)B_*H_*S_*S_];
__device__ float d_xpt  [S_*64*4];

// ---------------- block reduction ----------------------------------------
template<int NT>
__device__ __forceinline__ float blockSum(float v) {
    __shared__ float sh[NT/32];
    int lane = threadIdx.x & 31;
    int w    = threadIdx.x >> 5;
    #pragma unroll
    for (int o = 16; o > 0; o >>= 1) v += __shfl_xor_sync(0xffffffffu, v, o);
    if (lane == 0) sh[w] = v;
    __syncthreads();
    float tot = 0.f;
    #pragma unroll
    for (int i = 0; i < NT/32; i++) tot += sh[i];
    __syncthreads();
    return tot;
}

// ---------------- generic batched SGEMM (row-major, 128x128x8) -----------
// C[z] = A[z/aDiv] * B[z%bMod]; M,N multiples of 128; K multiple of 8.
__global__ __launch_bounds__(256, 2)
void sgemm_k(const float* __restrict__ A, const float* __restrict__ Bm,
             float* __restrict__ C, int M, int N, int K,
             long long sA, long long sB, long long sC, int aDiv, int bMod)
{
    A  += (long long)(blockIdx.z / aDiv) * sA;
    Bm += (long long)(blockIdx.z % bMod) * sB;
    C  += (long long)blockIdx.z * sC;

    __shared__ float As[8][128];
    __shared__ float Bs[8][128];

    int tid   = threadIdx.x;
    int a_row = tid >> 1;
    int a_col = (tid & 1) << 2;
    int b_row = tid >> 5;
    int b_col = (tid & 31) << 2;
    int trow  = (tid >> 4) << 3;
    int tcol  = (tid & 15) << 3;

    const float* Ap = A  + (long long)(blockIdx.y * 128 + a_row) * K + a_col;
    const float* Bp = Bm + (long long)b_row * N + blockIdx.x * 128 + b_col;

    float acc[8][8];
    #pragma unroll
    for (int i = 0; i < 8; i++)
        #pragma unroll
        for (int j = 0; j < 8; j++) acc[i][j] = 0.f;

    for (int k0 = 0; k0 < K; k0 += 8) {
        float4 av = *(const float4*)(Ap + k0);
        float4 bv = *(const float4*)(Bp + (long long)k0 * N);
        As[a_col + 0][a_row] = av.x;
        As[a_col + 1][a_row] = av.y;
        As[a_col + 2][a_row] = av.z;
        As[a_col + 3][a_row] = av.w;
        *(float4*)&Bs[b_row][b_col] = bv;
        __syncthreads();
        #pragma unroll
        for (int k = 0; k < 8; k++) {
            float ar[8], br[8];
            #pragma unroll
            for (int i = 0; i < 8; i++) ar[i] = As[k][trow + i];
            #pragma unroll
            for (int j = 0; j < 8; j++) br[j] = Bs[k][tcol + j];
            #pragma unroll
            for (int i = 0; i < 8; i++)
                #pragma unroll
                for (int j = 0; j < 8; j++)
                    acc[i][j] = fmaf(ar[i], br[j], acc[i][j]);
        }
        __syncthreads();
    }

    #pragma unroll
    for (int i = 0; i < 8; i++) {
        float* Cp = C + (long long)(blockIdx.y * 128 + trow + i) * N
                      + blockIdx.x * 128 + tcol;
        float4 v0 = make_float4(acc[i][0], acc[i][1], acc[i][2], acc[i][3]);
        float4 v1 = make_float4(acc[i][4], acc[i][5], acc[i][6], acc[i][7]);
        *(float4*)Cp       = v0;
        *((float4*)Cp + 1) = v1;
    }
}

// ---------------- layernorm (D=1024, 256 threads, 4 elems/thread) --------
__global__ void layernorm_k(const float* __restrict__ X, const float* __restrict__ w,
                            const float* __restrict__ b, float* __restrict__ out)
{
    size_t tok = blockIdx.x;
    const float* x = X + tok * D_;
    float vals[4];
    float s = 0.f;
    #pragma unroll
    for (int i = 0; i < 4; i++) { vals[i] = x[threadIdx.x + i*256]; s += vals[i]; }
    float mean = blockSum<256>(s) * (1.0f / D_);
    float vs = 0.f;
    #pragma unroll
    for (int i = 0; i < 4; i++) { float d = vals[i] - mean; vs += d*d; }
    float var = blockSum<256>(vs) * (1.0f / D_);
    float inv = rsqrtf(var + 1e-5f);
    float* o = out + tok * D_;
    #pragma unroll
    for (int i = 0; i < 4; i++) {
        int c = threadIdx.x + i*256;
        o[c] = (vals[i] - mean) * inv * w[c] + b[c];
    }
}

// ---------------- xpos table (fp64 trig for accuracy) ---------------------
__global__ void xpos_table_k(float* __restrict__ tab)
{
    int idx = blockIdx.x * 256 + threadIdx.x;
    if (idx >= S_ * 64) return;
    int i = idx & 63;
    int s = idx >> 6;
    double pos = (double)s;
    double sv  = (2.0*i + 0.4*128.0) / (1.4*128.0);
    double scl = pow(sv, pos / 512.0);
    float inv_freq_f = (float)pow(10000.0, -(double)i / 64.0);
    float ang_f = (float)s * inv_freq_f;       // mimic fp32 argument as in ref
    double ang = (double)ang_f;
    double sn = sin(ang), cs = cos(ang);
    tab[idx*4 + 0] = (float)(cs * scl);   // cos for Q
    tab[idx*4 + 1] = (float)(sn * scl);   // sin for Q
    tab[idx*4 + 2] = (float)(cs / scl);   // cos for K (downscale)
    tab[idx*4 + 3] = (float)(sn / scl);   // sin for K
}

// ---------------- apply xpos rotary to Q and K in place -------------------
__global__ void xpos_apply_k(float* __restrict__ Q, float* __restrict__ K,
                             const float* __restrict__ tab)
{
    long long idx = (long long)blockIdx.x * 256 + threadIdx.x;
    if (idx >= (long long)B_*H_*S_*64) return;
    int i = (int)(idx & 63);
    long long r = idx >> 6;
    int s = (int)(r % S_);
    long long base = r * 128 + 2*i;
    const float* t = tab + ((long long)s*64 + i) * 4;
    float cq = t[0], sq = t[1], ck = t[2], sk = t[3];
    float q1 = Q[base], q2 = Q[base+1];
    Q[base]   = q1*cq - q2*sq;
    Q[base+1] = q2*cq + q1*sq;
    float k1 = K[base], k2 = K[base+1];
    K[base]   = k1*ck - k2*sk;
    K[base+1] = k2*ck + k1*sk;
}

// ---------------- transpose per batch (rows x cols -> cols x rows) --------
__global__ void transpose_k(const float* __restrict__ in, float* __restrict__ out,
                            int rows, int cols)
{
    __shared__ float tile[32][33];
    const float* ib = in  + (long long)blockIdx.z * rows * cols;
    float*       ob = out + (long long)blockIdx.z * rows * cols;
    int r0 = blockIdx.x * 32, c0 = blockIdx.y * 32;
    int tx = threadIdx.x, ty = threadIdx.y;
    #pragma unroll
    for (int j = 0; j < 32; j += 8)
        tile[ty + j][tx] = ib[(long long)(r0 + ty + j) * cols + c0 + tx];
    __syncthreads();
    #pragma unroll
    for (int j = 0; j < 32; j += 8)
        ob[(long long)(c0 + ty + j) * rows + r0 + tx] = tile[tx][ty + j];
}

// ---------------- causal decay mask --------------------------------------
__global__ void decay_k(float* __restrict__ Sc)
{
    size_t idx = (size_t)blockIdx.x * 256 + threadIdx.x;
    if (idx >= (size_t)B_*H_*S_*S_) return;
    int t = (int)(idx & (S_ - 1));
    size_t r = idx >> 11;
    int s = (int)(r & (S_ - 1));
    int h = (int)((r >> 11) & (H_ - 1));
    if (t > s) { Sc[idx] = 0.f; return; }
    const float l32  = -3.4657359027997265f;   // ln(1/32)
    const float l512 = -6.2383246250395075f;   // ln(1/512)
    float frac = (float)h * (1.0f / 7.0f);
    float g = 1.0f - expf(l32 + (l512 - l32) * frac);
    float w = exp2f((float)(s - t) * log2f(g));
    Sc[idx] *= w;
}

// ---------------- groupnorm (per b,s,h over DV) + silu gate ---------------
__global__ void gnorm_gate_k(const float* __restrict__ Y, const float* __restrict__ G,
                             const float* __restrict__ w, const float* __restrict__ bb,
                             float* __restrict__ out)
{
    int h = blockIdx.x % H_;
    int s = (blockIdx.x / H_) % S_;
    int b = blockIdx.x / (H_ * S_);
    int v = threadIdx.x;

    size_t yoff = (((size_t)(b*H_ + h)) * S_ + s) * DV_ + v;
    float y = Y[yoff];
    float mean = blockSum<256>(y) * (1.0f / DV_);
    float d = y - mean;
    float var = blockSum<256>(d*d) * (1.0f / DV_);
    float yn = d * rsqrtf(var + 1e-5f);

    int col = h*DV_ + v;
    size_t goff = ((size_t)(b*S_ + s)) * VD_ + col;
    float g = G[goff];
    float gate = g / (1.0f + expf(-g));   // g * sigmoid(g)
    out[goff] = gate * (yn * w[col] + bb[col]);
}

// ---------------- elementwise helpers -------------------------------------
__global__ void add_k(float* __restrict__ a, const float* __restrict__ b, size_t n)
{
    size_t idx = (size_t)blockIdx.x * 256 + threadIdx.x;
    if (idx < n) a[idx] += b[idx];
}

__global__ void biasgelu_k(float* __restrict__ h, const float* __restrict__ b1)
{
    size_t idx = (size_t)blockIdx.x * 256 + threadIdx.x;
    if (idx >= (size_t)NT_ * FFN_) return;
    float x = h[idx] + b1[idx & (FFN_ - 1)];
    h[idx] = 0.5f * x * (1.0f + erff(x * 0.70710678118654752f));
}

__global__ void final_k(float* __restrict__ out, const float* __restrict__ b2,
                        const float* __restrict__ X2)
{
    size_t idx = (size_t)blockIdx.x * 256 + threadIdx.x;
    if (idx >= (size_t)NT_ * D_) return;
    out[idx] = out[idx] + b2[idx & (D_ - 1)] + X2[idx];
}

// ---------------- host launcher -------------------------------------------
extern "C" void kernel_launch(void* const* d_in, const int* in_sizes, int n_in,
                              void* d_out, int out_size)
{
    (void)in_sizes; (void)n_in; (void)out_size;
    const float* X      = (const float*)d_in[0];
    const float* Wq     = (const float*)d_in[1];
    const float* Wk     = (const float*)d_in[2];
    const float* Wv     = (const float*)d_in[3];
    const float* W_G    = (const float*)d_in[4];
    const float* W_O    = (const float*)d_in[5];
    const float* gn_w   = (const float*)d_in[6];
    const float* gn_b   = (const float*)d_in[7];
    const float* ln1_w  = (const float*)d_in[8];
    const float* ln1_b  = (const float*)d_in[9];
    const float* ln2_w  = (const float*)d_in[10];
    const float* ln2_b  = (const float*)d_in[11];
    const float* ffn_w1 = (const float*)d_in[12];
    const float* ffn_b1 = (const float*)d_in[13];
    const float* ffn_w2 = (const float*)d_in[14];
    const float* ffn_b2 = (const float*)d_in[15];
    float* out = (float*)d_out;

    float *Xn, *Q, *K, *Kt, *V, *G, *Y, *gated, *X2, *h1, *Sc, *xpt;
    cudaGetSymbolAddress((void**)&Xn,    d_Xn);
    cudaGetSymbolAddress((void**)&Q,     d_Q);
    cudaGetSymbolAddress((void**)&K,     d_K);
    cudaGetSymbolAddress((void**)&Kt,    d_Kt);
    cudaGetSymbolAddress((void**)&V,     d_V);
    cudaGetSymbolAddress((void**)&G,     d_G);
    cudaGetSymbolAddress((void**)&Y,     d_Y);
    cudaGetSymbolAddress((void**)&gated, d_gated);
    cudaGetSymbolAddress((void**)&X2,    d_X2);
    cudaGetSymbolAddress((void**)&h1,    d_h1);
    cudaGetSymbolAddress((void**)&Sc,    d_Sc);
    cudaGetSymbolAddress((void**)&xpt,   d_xpt);

    // 1) ln1
    layernorm_k<<<NT_, 256>>>(X, ln1_w, ln1_b, Xn);

    // 2) projections: Q,K (per-head), V (per-head), G (full)
    sgemm_k<<<dim3(1, 16, B_*H_), 256>>>(Xn, Wq, Q, S_, DK_, D_,
        (long long)S_*D_, (long long)D_*DK_, (long long)S_*DK_, H_, H_);
    sgemm_k<<<dim3(1, 16, B_*H_), 256>>>(Xn, Wk, K, S_, DK_, D_,
        (long long)S_*D_, (long long)D_*DK_, (long long)S_*DK_, H_, H_);
    sgemm_k<<<dim3(2, 16, B_*H_), 256>>>(Xn, Wv, V, S_, DV_, D_,
        (long long)S_*D_, (long long)D_*DV_, (long long)S_*DV_, H_, H_);
    sgemm_k<<<dim3(16, 32, 1), 256>>>(Xn, W_G, G, NT_, VD_, D_, 0, 0, 0, 1, 1);

    // 3) xpos rotary
    xpos_table_k<<<(S_*64 + 255)/256, 256>>>(xpt);
    xpos_apply_k<<<(B_*H_*S_*64)/256, 256>>>(Q, K, xpt);

    // 4) retention: scores = Q K^T (via K transpose), decay mask, Y = scores V
    transpose_k<<<dim3(S_/32, DK_/32, B_*H_), dim3(32, 8)>>>(K, Kt, S_, DK_);
    sgemm_k<<<dim3(16, 16, B_*H_), 256>>>(Q, Kt, Sc, S_, S_, DK_,
        (long long)S_*DK_, (long long)DK_*S_, (long long)S_*S_, 1, B_*H_);
    decay_k<<<(int)(((size_t)B_*H_*S_*S_)/256), 256>>>(Sc);
    sgemm_k<<<dim3(2, 16, B_*H_), 256>>>(Sc, V, Y, S_, DV_, S_,
        (long long)S_*S_, (long long)S_*DV_, (long long)S_*DV_, 1, B_*H_);

    // 5) groupnorm + silu gate
    gnorm_gate_k<<<B_*S_*H_, 256>>>(Y, G, gn_w, gn_b, gated);

    // 6) output projection + residual
    sgemm_k<<<dim3(8, 32, 1), 256>>>(gated, W_O, X2, NT_, D_, VD_, 0, 0, 0, 1, 1);
    add_k<<<(NT_*D_)/256, 256>>>(X2, X, (size_t)NT_*D_);

    // 7) ln2 + FFN (exact gelu) + residual
    layernorm_k<<<NT_, 256>>>(X2, ln2_w, ln2_b, Xn);
    sgemm_k<<<dim3(32, 32, 1), 256>>>(Xn, ffn_w1, h1, NT_, FFN_, D_, 0, 0, 0, 1, 1);
    biasgelu_k<<<(int)(((size_t)NT_*FFN_)/256), 256>>>(h1, ffn_b1);
    sgemm_k<<<dim3(8, 32, 1), 256>>>(h1, ffn_w2, out, NT_, D_, FFN_, 0, 0, 0, 1, 1);
    final_k<<<(NT_*D_)/256, 256>>>(out, ffn_b2, X2);
}

// round 4
// speedup vs baseline: 2.1669x; 2.1669x over previous
#include <cuda_runtime.h>
#include <math.h>

#define B_   2
#define S_   2048
#define D_   1024
#define H_   8
#define FFN_ 4096
#define DK_  128
#define VD_  2048
#define DV_  256
#define NT_  (B_*S_)

#define KC       32
#define TSTRIDE  80                 // bytes per smem tile row (16B-aligned, conflict-friendly)
#define TILE_B   (128*TSTRIDE)      // 10240 B
#define STAGE_B  (4*TILE_B)         // AH, AL, BH, BL
#define SMEM_TC  (2*STAGE_B)        // 81920 B

__device__ float d_Xn [B_*S_*D_];
__device__ float d_Q  [B_*H_*S_*DK_];
__device__ float d_K  [B_*H_*S_*DK_];
__device__ float d_V  [B_*H_*S_*DV_];
__device__ float d_G  [B_*S_*VD_];
__device__ float d_Y  [B_*H_*S_*DV_];
__device__ float d_X2 [B_*S_*D_];
__device__ float d_h1 [(size_t)B_*S_*FFN_];
__device__ float d_Sc [(size_t)B_*H_*S_*S_];
__device__ float d_xpt[S_*64*4];

__device__ __forceinline__ unsigned smem_u32(const void* p) {
    unsigned a;
    asm("{ .reg .u64 t; cvta.to.shared.u64 t, %1; cvt.u32.u64 %0, t; }"
        : "=r"(a) : "l"(p));
    return a;
}
__device__ __forceinline__ unsigned pack2(float a, float b) {
    unsigned r;
    asm("cvt.rn.bf16x2.f32 %0, %1, %2;" : "=r"(r) : "f"(b), "f"(a));
    return r;   // low 16 bits = a
}
__device__ __forceinline__ float blo(unsigned p){ return __uint_as_float(p<<16); }
__device__ __forceinline__ float bhi(unsigned p){ return __uint_as_float(p & 0xffff0000u); }

__device__ __forceinline__ void ldm_x4(unsigned* d, unsigned addr) {
    asm volatile("ldmatrix.sync.aligned.m8n8.x4.shared.b16 {%0,%1,%2,%3}, [%4];"
        : "=r"(d[0]), "=r"(d[1]), "=r"(d[2]), "=r"(d[3]) : "r"(addr));
}
__device__ __forceinline__ void ldm_x2(unsigned* d, unsigned addr) {
    asm volatile("ldmatrix.sync.aligned.m8n8.x2.shared.b16 {%0,%1}, [%2];"
        : "=r"(d[0]), "=r"(d[1]) : "r"(addr));
}
__device__ __forceinline__ void mma16816(float* c, const unsigned* a, const unsigned* b) {
    asm volatile("mma.sync.aligned.m16n8k16.row.col.f32.bf16.bf16.f32 "
        "{%0,%1,%2,%3}, {%4,%5,%6,%7}, {%8,%9}, {%0,%1,%2,%3};"
        : "+f"(c[0]), "+f"(c[1]), "+f"(c[2]), "+f"(c[3])
        : "r"(a[0]), "r"(a[1]), "r"(a[2]), "r"(a[3]), "r"(b[0]), "r"(b[1]));
}

// ================= generic tensor-core GEMM ================================
// C[z] = A[z/aDiv] * B[z%bMod]; A row-major [M,K].
// bT=0: B row-major [K,N].  bT=1: B given as [N,K] row-major (i.e. B^T).
// mode 0 plain; 1 scores (causal tile skip + decay epilogue);
//      2 retV (K limited to (by+1)*128); 3 bias + exact GELU epilogue.
__global__ __launch_bounds__(256, 1)
void tcgemm(const float* __restrict__ A, const float* __restrict__ Bm,
            float* __restrict__ C, const float* __restrict__ bias,
            int N, int K, long long sA, long long sB, long long sC,
            int aDiv, int bMod, int mode, int bT)
{
    int bx = blockIdx.x, by = blockIdx.y, bz = blockIdx.z;
    if (mode == 1 && bx > by) return;

    A  += (long long)(bz / aDiv) * sA;
    Bm += (long long)(bz % bMod) * sB;
    C  += (long long)bz * sC;
    int Kuse = (mode == 2) ? min(K, (by + 1) * 128) : K;
    int nch  = Kuse / KC;

    extern __shared__ char smem[];
    int tid = threadIdx.x, wid = tid >> 5, lane = tid & 31;
    int r  = tid & 127;        // tile row (A) / tile n (B^T) owned by this thread
    int kh = tid >> 7;         // 0/1: which k16 half of the chunk

    const float* Ag  = A  + (long long)(by * 128 + r) * K + kh * 16;
    const float* BgT = Bm + (long long)(bx * 128 + r) * K + kh * 16;  // bT=1
    const float* Bg  = Bm + (long long)(kh * 16) * N + bx * 128 + r;  // bT=0

    float fa[16], fb[16];

    auto ldg = [&](int c) {
        const float4* pa = (const float4*)(Ag + c * KC);
        #pragma unroll
        for (int j = 0; j < 4; j++) {
            float4 v = pa[j];
            fa[4*j] = v.x; fa[4*j+1] = v.y; fa[4*j+2] = v.z; fa[4*j+3] = v.w;
        }
        if (bT) {
            const float4* pb = (const float4*)(BgT + c * KC);
            #pragma unroll
            for (int j = 0; j < 4; j++) {
                float4 v = pb[j];
                fb[4*j] = v.x; fb[4*j+1] = v.y; fb[4*j+2] = v.z; fb[4*j+3] = v.w;
            }
        } else {
            #pragma unroll
            for (int i = 0; i < 16; i++)
                fb[i] = Bg[(long long)(c * KC + i) * N];
        }
    };

    auto sts = [&](int st) {
        char* base = smem + st * STAGE_B;
        unsigned off = (unsigned)r * TSTRIDE + (unsigned)kh * 32;
        unsigned h[8], l[8];
        #pragma unroll
        for (int j = 0; j < 8; j++) {
            h[j] = pack2(fa[2*j], fa[2*j+1]);
            l[j] = pack2(fa[2*j] - blo(h[j]), fa[2*j+1] - bhi(h[j]));
        }
        *(uint4*)(base + off)               = make_uint4(h[0],h[1],h[2],h[3]);
        *(uint4*)(base + off + 16)          = make_uint4(h[4],h[5],h[6],h[7]);
        *(uint4*)(base + TILE_B + off)      = make_uint4(l[0],l[1],l[2],l[3]);
        *(uint4*)(base + TILE_B + off + 16) = make_uint4(l[4],l[5],l[6],l[7]);
        #pragma unroll
        for (int j = 0; j < 8; j++) {
            h[j] = pack2(fb[2*j], fb[2*j+1]);
            l[j] = pack2(fb[2*j] - blo(h[j]), fb[2*j+1] - bhi(h[j]));
        }
        *(uint4*)(base + 2*TILE_B + off)      = make_uint4(h[0],h[1],h[2],h[3]);
        *(uint4*)(base + 2*TILE_B + off + 16) = make_uint4(h[4],h[5],h[6],h[7]);
        *(uint4*)(base + 3*TILE_B + off)      = make_uint4(l[0],l[1],l[2],l[3]);
        *(uint4*)(base + 3*TILE_B + off + 16) = make_uint4(l[4],l[5],l[6],l[7]);
    };

    int wm = (wid >> 2) * 64;    // warp m offset in block tile
    int wn = (wid & 3) * 32;     // warp n offset
    float acc[4][4][4];
    #pragma unroll
    for (int i = 0; i < 4; i++)
        #pragma unroll
        for (int j = 0; j < 4; j++)
            #pragma unroll
            for (int q = 0; q < 4; q++) acc[i][j][q] = 0.f;

    unsigned sbase = smem_u32(smem);

    auto mma_chunk = [&](int st) {
        unsigned sb = sbase + st * STAGE_B;
        #pragma unroll
        for (int ks = 0; ks < 2; ks++) {
            unsigned kbyte = ks * 32;
            unsigned ah[4][4], al[4][4], bh[4][2], bl[4][2];
            #pragma unroll
            for (int mt = 0; mt < 4; mt++) {
                unsigned row  = wm + mt*16 + (lane & 15);
                unsigned addr = sb + row * TSTRIDE + kbyte + ((lane >> 4) << 4);
                ldm_x4(ah[mt], addr);
                ldm_x4(al[mt], addr + TILE_B);
            }
            #pragma unroll
            for (int nt = 0; nt < 4; nt++) {
                unsigned row  = wn + nt*8 + (lane & 7);
                unsigned addr = sb + 2*TILE_B + row * TSTRIDE + kbyte + (((lane >> 3) & 1) << 4);
                ldm_x2(bh[nt], addr);
                ldm_x2(bl[nt], addr + TILE_B);
            }
            #pragma unroll
            for (int mt = 0; mt < 4; mt++)
                #pragma unroll
                for (int nt = 0; nt < 4; nt++) {
                    mma16816(acc[mt][nt], ah[mt], bh[nt]);
                    mma16816(acc[mt][nt], ah[mt], bl[nt]);
                    mma16816(acc[mt][nt], al[mt], bh[nt]);
                }
        }
    };

    ldg(0);
    sts(0);
    __syncthreads();
    for (int c = 0; c < nch; c++) {
        if (c + 1 < nch) ldg(c + 1);
        mma_chunk(c & 1);
        if (c + 1 < nch) sts((c + 1) & 1);
        __syncthreads();
    }

    // ---------------- epilogue ----------------
    float lg2g = 0.f;
    if (mode == 1) {
        const float l32 = -3.4657359027997265f, l512 = -6.2383246250395075f;
        float g = 1.0f - expf(l32 + (l512 - l32) * (float)(bz & (H_-1)) * (1.0f/7.0f));
        lg2g = log2f(g);
    }
    int rbase = by * 128 + wm + (lane >> 2);
    int cbase = bx * 128 + wn + (lane & 3) * 2;
    #pragma unroll
    for (int mt = 0; mt < 4; mt++) {
        #pragma unroll
        for (int half = 0; half < 2; half++) {
            int grow = rbase + mt*16 + half*8;
            #pragma unroll
            for (int nt = 0; nt < 4; nt++) {
                float v0 = acc[mt][nt][half*2], v1 = acc[mt][nt][half*2+1];
                int gcol = cbase + nt*8;
                if (mode == 1) {
                    int d0 = grow - gcol, d1 = d0 - 1;
                    v0 = (d0 >= 0) ? v0 * exp2f((float)d0 * lg2g) : 0.f;
                    v1 = (d1 >= 0) ? v1 * exp2f((float)d1 * lg2g) : 0.f;
                } else if (mode == 3) {
                    float x0 = v0 + bias[gcol], x1 = v1 + bias[gcol+1];
                    v0 = 0.5f*x0*(1.0f + erff(x0*0.70710678118654752f));
                    v1 = 0.5f*x1*(1.0f + erff(x1*0.70710678118654752f));
                }
                *(float2*)(C + (long long)grow * N + gcol) = make_float2(v0, v1);
            }
        }
    }
}

// ---------------- elementwise ----------------------------------------------
template<int NT>
__device__ __forceinline__ float blockSum(float v) {
    __shared__ float sh[NT/32];
    int lane = threadIdx.x & 31, w = threadIdx.x >> 5;
    #pragma unroll
    for (int o = 16; o > 0; o >>= 1) v += __shfl_xor_sync(0xffffffffu, v, o);
    if (lane == 0) sh[w] = v;
    __syncthreads();
    float t = 0.f;
    #pragma unroll
    for (int i = 0; i < NT/32; i++) t += sh[i];
    __syncthreads();
    return t;
}

__global__ void layernorm_k(const float* __restrict__ X, const float* __restrict__ w,
                            const float* __restrict__ b, float* __restrict__ out)
{
    size_t tok = blockIdx.x;
    const float* x = X + tok * D_;
    float vals[4], s = 0.f;
    #pragma unroll
    for (int i = 0; i < 4; i++) { vals[i] = x[threadIdx.x + i*256]; s += vals[i]; }
    float mean = blockSum<256>(s) * (1.0f / D_);
    float vs = 0.f;
    #pragma unroll
    for (int i = 0; i < 4; i++) { float d = vals[i]-mean; vs += d*d; }
    float inv = rsqrtf(blockSum<256>(vs) * (1.0f / D_) + 1e-5f);
    float* o = out + tok * D_;
    #pragma unroll
    for (int i = 0; i < 4; i++) {
        int c = threadIdx.x + i*256;
        o[c] = (vals[i]-mean) * inv * w[c] + b[c];
    }
}

__global__ void xpos_table_k(float* __restrict__ tab)
{
    int idx = blockIdx.x * 256 + threadIdx.x;
    if (idx >= S_ * 64) return;
    int i = idx & 63, s = idx >> 6;
    double scl = pow((2.0*i + 51.2) / 179.2, (double)s / 512.0);
    float ang_f = (float)s * (float)pow(10000.0, -(double)i / 64.0);
    double sn = sin((double)ang_f), cs = cos((double)ang_f);
    tab[idx*4+0] = (float)(cs * scl);  tab[idx*4+1] = (float)(sn * scl);
    tab[idx*4+2] = (float)(cs / scl);  tab[idx*4+3] = (float)(sn / scl);
}

__global__ void xpos_apply_k(float* __restrict__ Q, float* __restrict__ K,
                             const float* __restrict__ tab)
{
    long long idx = (long long)blockIdx.x * 256 + threadIdx.x;
    if (idx >= (long long)B_*H_*S_*64) return;
    int i = (int)(idx & 63);
    long long rr = idx >> 6;
    int s = (int)(rr % S_);
    long long base = rr * 128 + 2*i;
    const float* t = tab + ((long long)s*64 + i) * 4;
    float q1 = Q[base], q2 = Q[base+1];
    Q[base]   = q1*t[0] - q2*t[1];
    Q[base+1] = q2*t[0] + q1*t[1];
    float k1 = K[base], k2 = K[base+1];
    K[base]   = k1*t[2] - k2*t[3];
    K[base+1] = k2*t[2] + k1*t[3];
}

__global__ void gnorm_gate_k(const float* __restrict__ Y, float* __restrict__ G,
                             const float* __restrict__ w, const float* __restrict__ bb)
{
    int h = blockIdx.x % H_, s = (blockIdx.x / H_) % S_, b = blockIdx.x / (H_*S_);
    int v = threadIdx.x;
    size_t yoff = (((size_t)(b*H_+h))*S_ + s)*DV_ + v;
    float y = Y[yoff];
    float mean = blockSum<256>(y) * (1.0f/DV_);
    float d = y - mean;
    float yn = d * rsqrtf(blockSum<256>(d*d)*(1.0f/DV_) + 1e-5f);
    int col = h*DV_ + v;
    size_t goff = ((size_t)(b*S_+s))*VD_ + col;
    float g = G[goff];
    G[goff] = (g / (1.0f + expf(-g))) * (yn * w[col] + bb[col]);
}

__global__ void add_k(float* __restrict__ a, const float* __restrict__ b, size_t n)
{
    size_t i = (size_t)blockIdx.x * 256 + threadIdx.x;
    if (i < n) a[i] += b[i];
}

__global__ void final_k(float* __restrict__ out, const float* __restrict__ b2,
                        const float* __restrict__ X2)
{
    size_t i = (size_t)blockIdx.x * 256 + threadIdx.x;
    if (i >= (size_t)NT_ * D_) return;
    out[i] = out[i] + b2[i & (D_-1)] + X2[i];
}

// ---------------- host launcher --------------------------------------------
extern "C" void kernel_launch(void* const* d_in, const int* in_sizes, int n_in,
                              void* d_out, int out_size)
{
    (void)in_sizes; (void)n_in; (void)out_size;
    const float* X      = (const float*)d_in[0];
    const float* Wq     = (const float*)d_in[1];
    const float* Wk     = (const float*)d_in[2];
    const float* Wv     = (const float*)d_in[3];
    const float* W_G    = (const float*)d_in[4];
    const float* W_O    = (const float*)d_in[5];
    const float* gn_w   = (const float*)d_in[6];
    const float* gn_b   = (const float*)d_in[7];
    const float* ln1_w  = (const float*)d_in[8];
    const float* ln1_b  = (const float*)d_in[9];
    const float* ln2_w  = (const float*)d_in[10];
    const float* ln2_b  = (const float*)d_in[11];
    const float* ffn_w1 = (const float*)d_in[12];
    const float* ffn_b1 = (const float*)d_in[13];
    const float* ffn_w2 = (const float*)d_in[14];
    const float* ffn_b2 = (const float*)d_in[15];
    float* out = (float*)d_out;

    float *Xn,*Q,*K,*V,*G,*Y,*X2,*h1,*Sc,*xpt;
    cudaGetSymbolAddress((void**)&Xn,  d_Xn);
    cudaGetSymbolAddress((void**)&Q,   d_Q);
    cudaGetSymbolAddress((void**)&K,   d_K);
    cudaGetSymbolAddress((void**)&V,   d_V);
    cudaGetSymbolAddress((void**)&G,   d_G);
    cudaGetSymbolAddress((void**)&Y,   d_Y);
    cudaGetSymbolAddress((void**)&X2,  d_X2);
    cudaGetSymbolAddress((void**)&h1,  d_h1);
    cudaGetSymbolAddress((void**)&Sc,  d_Sc);
    cudaGetSymbolAddress((void**)&xpt, d_xpt);

    cudaFuncSetAttribute(tcgemm, cudaFuncAttributeMaxDynamicSharedMemorySize, SMEM_TC);

    layernorm_k<<<NT_, 256>>>(X, ln1_w, ln1_b, Xn);

    // projections
    tcgemm<<<dim3(1,16,B_*H_), 256, SMEM_TC>>>(Xn, Wq, Q, nullptr, DK_, D_,
        (long long)S_*D_, (long long)D_*DK_, (long long)S_*DK_, H_, H_, 0, 0);
    tcgemm<<<dim3(1,16,B_*H_), 256, SMEM_TC>>>(Xn, Wk, K, nullptr, DK_, D_,
        (long long)S_*D_, (long long)D_*DK_, (long long)S_*DK_, H_, H_, 0, 0);
    tcgemm<<<dim3(2,16,B_*H_), 256, SMEM_TC>>>(Xn, Wv, V, nullptr, DV_, D_,
        (long long)S_*D_, (long long)D_*DV_, (long long)S_*DV_, H_, H_, 0, 0);
    tcgemm<<<dim3(16,32,1), 256, SMEM_TC>>>(Xn, W_G, G, nullptr, VD_, D_,
        0, 0, 0, 1, 1, 0, 0);

    // xpos rotary
    xpos_table_k<<<(S_*64+255)/256, 256>>>(xpt);
    xpos_apply_k<<<(B_*H_*S_*64)/256, 256>>>(Q, K, xpt);

    // retention: scores = Q K^T (K used directly as B^T), fused decay; Y = Sc V
    tcgemm<<<dim3(16,16,B_*H_), 256, SMEM_TC>>>(Q, K, Sc, nullptr, S_, DK_,
        (long long)S_*DK_, (long long)S_*DK_, (long long)S_*S_, 1, B_*H_, 1, 1);
    tcgemm<<<dim3(2,16,B_*H_), 256, SMEM_TC>>>(Sc, V, Y, nullptr, DV_, S_,
        (long long)S_*S_, (long long)S_*DV_, (long long)S_*DV_, 1, B_*H_, 2, 0);

    // groupnorm + silu gate (in place into G)
    gnorm_gate_k<<<B_*S_*H_, 256>>>(Y, G, gn_w, gn_b);

    // output projection + residual
    tcgemm<<<dim3(8,32,1), 256, SMEM_TC>>>(G, W_O, X2, nullptr, D_, VD_,
        0, 0, 0, 1, 1, 0, 0);
    add_k<<<(NT_*D_)/256, 256>>>(X2, X, (size_t)NT_*D_);

    // ln2 + FFN
    layernorm_k<<<NT_, 256>>>(X2, ln2_w, ln2_b, Xn);
    tcgemm<<<dim3(32,32,1), 256, SMEM_TC>>>(Xn, ffn_w1, h1, ffn_b1, FFN_, D_,
        0, 0, 0, 1, 1, 3, 0);
    tcgemm<<<dim3(8,32,1), 256, SMEM_TC>>>(h1, ffn_w2, out, nullptr, D_, FFN_,
        0, 0, 0, 1, 1, 0, 0);
    final_k<<<(NT_*D_)/256, 256>>>(out, ffn_b2, X2);
}

// round 5
// speedup vs baseline: 2.2227x; 1.0258x over previous
#include <cuda_runtime.h>
#include <math.h>

#define B_   2
#define S_   2048
#define D_   1024
#define H_   8
#define FFN_ 4096
#define DK_  128
#define VD_  2048
#define DV_  256
#define NT_  (B_*S_)

#define KC       32
#define TSTRIDE  80
#define TILE_B   (128*TSTRIDE)      // 10240 B
#define STAGE_B  (4*TILE_B)         // AH, AL, BH, BL
#define SMEM_TC  (2*STAGE_B)        // 81920 B
#define NTHREADS 512

__device__ float d_Xn [B_*S_*D_];
__device__ float d_Q  [B_*H_*S_*DK_];
__device__ float d_K  [B_*H_*S_*DK_];
__device__ float d_V  [B_*H_*S_*DV_];
__device__ float d_G  [B_*S_*VD_];
__device__ float d_Y  [B_*H_*S_*DV_];
__device__ float d_X2 [B_*S_*D_];
__device__ float d_h1 [(size_t)B_*S_*FFN_];
__device__ float d_Sc [(size_t)B_*H_*S_*S_];
__device__ float d_xpt[S_*64*4];

__device__ __forceinline__ unsigned smem_u32(const void* p) {
    unsigned a;
    asm("{ .reg .u64 t; cvta.to.shared.u64 t, %1; cvt.u32.u64 %0, t; }"
        : "=r"(a) : "l"(p));
    return a;
}
__device__ __forceinline__ unsigned pack2(float a, float b) {
    unsigned r;
    asm("cvt.rn.bf16x2.f32 %0, %1, %2;" : "=r"(r) : "f"(b), "f"(a));
    return r;   // low 16 = a
}
__device__ __forceinline__ float blo(unsigned p){ return __uint_as_float(p<<16); }
__device__ __forceinline__ float bhi(unsigned p){ return __uint_as_float(p & 0xffff0000u); }

__device__ __forceinline__ void ldm_x4(unsigned* d, unsigned addr) {
    asm volatile("ldmatrix.sync.aligned.m8n8.x4.shared.b16 {%0,%1,%2,%3}, [%4];"
        : "=r"(d[0]), "=r"(d[1]), "=r"(d[2]), "=r"(d[3]) : "r"(addr));
}
__device__ __forceinline__ void mma16816(float* c, const unsigned* a, const unsigned* b) {
    asm volatile("mma.sync.aligned.m16n8k16.row.col.f32.bf16.bf16.f32 "
        "{%0,%1,%2,%3}, {%4,%5,%6,%7}, {%8,%9}, {%0,%1,%2,%3};"
        : "+f"(c[0]), "+f"(c[1]), "+f"(c[2]), "+f"(c[3])
        : "r"(a[0]), "r"(a[1]), "r"(a[2]), "r"(a[3]), "r"(b[0]), "r"(b[1]));
}

// ================= generic tensor-core GEMM (512 thr, 32x32 warp tiles) ====
// C[z] = A[z/aDiv] * B[z%bMod]; A row-major [M,K].
// bT=0: B row-major [K,N].  bT=1: B given as [N,K] row-major (B^T).
// mode 0 plain; 1 scores (causal tile skip + decay); 2 retV (K limit);
//      3 bias + exact GELU.
__global__ __launch_bounds__(NTHREADS, 1)
void tcgemm(const float* __restrict__ A, const float* __restrict__ Bm,
            float* __restrict__ C, const float* __restrict__ bias,
            int N, int K, long long sA, long long sB, long long sC,
            int aDiv, int bMod, int mode, int bT)
{
    int bx = blockIdx.x, by = blockIdx.y, bz = blockIdx.z;
    if (mode == 1 && bx > by) return;

    A  += (long long)(bz / aDiv) * sA;
    Bm += (long long)(bz % bMod) * sB;
    C  += (long long)bz * sC;
    int Kuse = (mode == 2) ? min(K, (by + 1) * 128) : K;
    int nch  = Kuse / KC;

    extern __shared__ char smem[];
    int tid = threadIdx.x, wid = tid >> 5, lane = tid & 31;
    int r = tid & 127;          // tile row (A) / tile n (B^T)
    int q = tid >> 7;           // 0..3: which 8-wide k slice of the chunk

    const float* Ag  = A  + (long long)(by * 128 + r) * K + q * 8;
    const float* BgT = Bm + (long long)(bx * 128 + r) * K + q * 8;
    const float* Bg  = Bm + (long long)(q * 8) * N + bx * 128 + r;

    float fa[8], fb[8];

    auto ldg = [&](int c) {
        const float4* pa = (const float4*)(Ag + c * KC);
        float4 v0 = pa[0], v1 = pa[1];
        fa[0]=v0.x; fa[1]=v0.y; fa[2]=v0.z; fa[3]=v0.w;
        fa[4]=v1.x; fa[5]=v1.y; fa[6]=v1.z; fa[7]=v1.w;
        if (bT) {
            const float4* pb = (const float4*)(BgT + c * KC);
            float4 w0 = pb[0], w1 = pb[1];
            fb[0]=w0.x; fb[1]=w0.y; fb[2]=w0.z; fb[3]=w0.w;
            fb[4]=w1.x; fb[5]=w1.y; fb[6]=w1.z; fb[7]=w1.w;
        } else {
            const float* p = Bg + (long long)(c * KC) * N;
            #pragma unroll
            for (int i = 0; i < 8; i++) fb[i] = p[(long long)i * N];
        }
    };

    auto sts = [&](int st) {
        char* base = smem + st * STAGE_B;
        unsigned off = (unsigned)r * TSTRIDE + (unsigned)q * 16;
        unsigned h0 = pack2(fa[0],fa[1]), h1 = pack2(fa[2],fa[3]);
        unsigned h2 = pack2(fa[4],fa[5]), h3 = pack2(fa[6],fa[7]);
        *(uint4*)(base + off) = make_uint4(h0,h1,h2,h3);
        *(uint4*)(base + TILE_B + off) = make_uint4(
            pack2(fa[0]-blo(h0), fa[1]-bhi(h0)), pack2(fa[2]-blo(h1), fa[3]-bhi(h1)),
            pack2(fa[4]-blo(h2), fa[5]-bhi(h2)), pack2(fa[6]-blo(h3), fa[7]-bhi(h3)));
        h0 = pack2(fb[0],fb[1]); h1 = pack2(fb[2],fb[3]);
        h2 = pack2(fb[4],fb[5]); h3 = pack2(fb[6],fb[7]);
        *(uint4*)(base + 2*TILE_B + off) = make_uint4(h0,h1,h2,h3);
        *(uint4*)(base + 3*TILE_B + off) = make_uint4(
            pack2(fb[0]-blo(h0), fb[1]-bhi(h0)), pack2(fb[2]-blo(h1), fb[3]-bhi(h1)),
            pack2(fb[4]-blo(h2), fb[5]-bhi(h2)), pack2(fb[6]-blo(h3), fb[7]-bhi(h3)));
    };

    int wm = (wid >> 2) * 32;   // warp m offset
    int wn = (wid & 3) * 32;    // warp n offset
    float acc[2][4][4];
    #pragma unroll
    for (int i = 0; i < 2; i++)
        #pragma unroll
        for (int j = 0; j < 4; j++)
            #pragma unroll
            for (int p = 0; p < 4; p++) acc[i][j][p] = 0.f;

    unsigned sbase = smem_u32(smem);
    // lane-derived ldmatrix offsets
    unsigned a_off = (unsigned)((lane & 15) * TSTRIDE + ((lane >> 4) << 4));
    unsigned b_off = (unsigned)(((lane & 7) + ((lane >> 4) << 3)) * TSTRIDE
                                + (((lane >> 3) & 1) << 4));

    auto mma_half = [&](unsigned sb, int ks) {
        unsigned kb = (unsigned)ks * 32;
        unsigned ah[2][4], al[2][4], bb[2][4];
        #pragma unroll
        for (int mt = 0; mt < 2; mt++)
            ldm_x4(ah[mt], sb + (unsigned)(wm + mt*16) * TSTRIDE + a_off + kb);
        #pragma unroll
        for (int p = 0; p < 2; p++)
            ldm_x4(bb[p], sb + 2*TILE_B + (unsigned)(wn + p*16) * TSTRIDE + b_off + kb);
        #pragma unroll
        for (int mt = 0; mt < 2; mt++)
            #pragma unroll
            for (int nt = 0; nt < 4; nt++)
                mma16816(acc[mt][nt], ah[mt], &bb[nt>>1][(nt&1)*2]);
        #pragma unroll
        for (int mt = 0; mt < 2; mt++)
            ldm_x4(al[mt], sb + TILE_B + (unsigned)(wm + mt*16) * TSTRIDE + a_off + kb);
        #pragma unroll
        for (int mt = 0; mt < 2; mt++)
            #pragma unroll
            for (int nt = 0; nt < 4; nt++)
                mma16816(acc[mt][nt], al[mt], &bb[nt>>1][(nt&1)*2]);
        #pragma unroll
        for (int p = 0; p < 2; p++)
            ldm_x4(bb[p], sb + 3*TILE_B + (unsigned)(wn + p*16) * TSTRIDE + b_off + kb);
        #pragma unroll
        for (int mt = 0; mt < 2; mt++)
            #pragma unroll
            for (int nt = 0; nt < 4; nt++)
                mma16816(acc[mt][nt], ah[mt], &bb[nt>>1][(nt&1)*2]);
    };

    ldg(0);
    sts(0);
    __syncthreads();
    for (int c = 0; c < nch; c++) {
        bool more = (c + 1 < nch);
        if (more) ldg(c + 1);
        unsigned sb = sbase + (unsigned)(c & 1) * STAGE_B;
        mma_half(sb, 0);
        if (more) sts((c + 1) & 1);
        mma_half(sb, 1);
        __syncthreads();
    }

    // ---------------- epilogue ----------------
    float lg2g = 0.f;
    if (mode == 1) {
        const float l32 = -3.4657359027997265f, l512 = -6.2383246250395075f;
        float g = 1.0f - expf(l32 + (l512 - l32) * (float)(bz & (H_-1)) * (1.0f/7.0f));
        lg2g = log2f(g);
    }
    int rbase = by * 128 + wm + (lane >> 2);
    int cbase = bx * 128 + wn + (lane & 3) * 2;
    #pragma unroll
    for (int mt = 0; mt < 2; mt++) {
        #pragma unroll
        for (int half = 0; half < 2; half++) {
            int grow = rbase + mt*16 + half*8;
            #pragma unroll
            for (int nt = 0; nt < 4; nt++) {
                float v0 = acc[mt][nt][half*2], v1 = acc[mt][nt][half*2+1];
                int gcol = cbase + nt*8;
                if (mode == 1) {
                    int d0 = grow - gcol, d1 = d0 - 1;
                    v0 = (d0 >= 0) ? v0 * exp2f((float)d0 * lg2g) : 0.f;
                    v1 = (d1 >= 0) ? v1 * exp2f((float)d1 * lg2g) : 0.f;
                } else if (mode == 3) {
                    float x0 = v0 + bias[gcol], x1 = v1 + bias[gcol+1];
                    v0 = 0.5f*x0*(1.0f + erff(x0*0.70710678118654752f));
                    v1 = 0.5f*x1*(1.0f + erff(x1*0.70710678118654752f));
                }
                *(float2*)(C + (long long)grow * N + gcol) = make_float2(v0, v1);
            }
        }
    }
}

// ---------------- elementwise ----------------------------------------------
template<int NT>
__device__ __forceinline__ float blockSum(float v) {
    __shared__ float sh[NT/32];
    int lane = threadIdx.x & 31, w = threadIdx.x >> 5;
    #pragma unroll
    for (int o = 16; o > 0; o >>= 1) v += __shfl_xor_sync(0xffffffffu, v, o);
    if (lane == 0) sh[w] = v;
    __syncthreads();
    float t = 0.f;
    #pragma unroll
    for (int i = 0; i < NT/32; i++) t += sh[i];
    __syncthreads();
    return t;
}

__global__ void layernorm_k(const float* __restrict__ X, const float* __restrict__ w,
                            const float* __restrict__ b, float* __restrict__ out)
{
    size_t tok = blockIdx.x;
    const float* x = X + tok * D_;
    float vals[4], s = 0.f;
    #pragma unroll
    for (int i = 0; i < 4; i++) { vals[i] = x[threadIdx.x + i*256]; s += vals[i]; }
    float mean = blockSum<256>(s) * (1.0f / D_);
    float vs = 0.f;
    #pragma unroll
    for (int i = 0; i < 4; i++) { float d = vals[i]-mean; vs += d*d; }
    float inv = rsqrtf(blockSum<256>(vs) * (1.0f / D_) + 1e-5f);
    float* o = out + tok * D_;
    #pragma unroll
    for (int i = 0; i < 4; i++) {
        int c = threadIdx.x + i*256;
        o[c] = (vals[i]-mean) * inv * w[c] + b[c];
    }
}

__global__ void xpos_table_k(float* __restrict__ tab)
{
    int idx = blockIdx.x * 256 + threadIdx.x;
    if (idx >= S_ * 64) return;
    int i = idx & 63, s = idx >> 6;
    double scl = pow((2.0*i + 51.2) / 179.2, (double)s / 512.0);
    float ang_f = (float)s * (float)pow(10000.0, -(double)i / 64.0);
    double sn = sin((double)ang_f), cs = cos((double)ang_f);
    tab[idx*4+0] = (float)(cs * scl);  tab[idx*4+1] = (float)(sn * scl);
    tab[idx*4+2] = (float)(cs / scl);  tab[idx*4+3] = (float)(sn / scl);
}

__global__ void xpos_apply_k(float* __restrict__ Q, float* __restrict__ K,
                             const float* __restrict__ tab)
{
    long long idx = (long long)blockIdx.x * 256 + threadIdx.x;
    if (idx >= (long long)B_*H_*S_*64) return;
    int i = (int)(idx & 63);
    long long rr = idx >> 6;
    int s = (int)(rr % S_);
    long long base = rr * 128 + 2*i;
    const float* t = tab + ((long long)s*64 + i) * 4;
    float q1 = Q[base], q2 = Q[base+1];
    Q[base]   = q1*t[0] - q2*t[1];
    Q[base+1] = q2*t[0] + q1*t[1];
    float k1 = K[base], k2 = K[base+1];
    K[base]   = k1*t[2] - k2*t[3];
    K[base+1] = k2*t[2] + k1*t[3];
}

__global__ void gnorm_gate_k(const float* __restrict__ Y, float* __restrict__ G,
                             const float* __restrict__ w, const float* __restrict__ bb)
{
    int h = blockIdx.x % H_, s = (blockIdx.x / H_) % S_, b = blockIdx.x / (H_*S_);
    int v = threadIdx.x;
    size_t yoff = (((size_t)(b*H_+h))*S_ + s)*DV_ + v;
    float y = Y[yoff];
    float mean = blockSum<256>(y) * (1.0f/DV_);
    float d = y - mean;
    float yn = d * rsqrtf(blockSum<256>(d*d)*(1.0f/DV_) + 1e-5f);
    int col = h*DV_ + v;
    size_t goff = ((size_t)(b*S_+s))*VD_ + col;
    float g = G[goff];
    G[goff] = (g / (1.0f + expf(-g))) * (yn * w[col] + bb[col]);
}

__global__ void add_k(float* __restrict__ a, const float* __restrict__ b, size_t n)
{
    size_t i = (size_t)blockIdx.x * 256 + threadIdx.x;
    if (i < n) a[i] += b[i];
}

__global__ void final_k(float* __restrict__ out, const float* __restrict__ b2,
                        const float* __restrict__ X2)
{
    size_t i = (size_t)blockIdx.x * 256 + threadIdx.x;
    if (i >= (size_t)NT_ * D_) return;
    out[i] = out[i] + b2[i & (D_-1)] + X2[i];
}

// ---------------- host launcher --------------------------------------------
extern "C" void kernel_launch(void* const* d_in, const int* in_sizes, int n_in,
                              void* d_out, int out_size)
{
    (void)in_sizes; (void)n_in; (void)out_size;
    const float* X      = (const float*)d_in[0];
    const float* Wq     = (const float*)d_in[1];
    const float* Wk     = (const float*)d_in[2];
    const float* Wv     = (const float*)d_in[3];
    const float* W_G    = (const float*)d_in[4];
    const float* W_O    = (const float*)d_in[5];
    const float* gn_w   = (const float*)d_in[6];
    const float* gn_b   = (const float*)d_in[7];
    const float* ln1_w  = (const float*)d_in[8];
    const float* ln1_b  = (const float*)d_in[9];
    const float* ln2_w  = (const float*)d_in[10];
    const float* ln2_b  = (const float*)d_in[11];
    const float* ffn_w1 = (const float*)d_in[12];
    const float* ffn_b1 = (const float*)d_in[13];
    const float* ffn_w2 = (const float*)d_in[14];
    const float* ffn_b2 = (const float*)d_in[15];
    float* out = (float*)d_out;

    float *Xn,*Q,*K,*V,*G,*Y,*X2,*h1,*Sc,*xpt;
    cudaGetSymbolAddress((void**)&Xn,  d_Xn);
    cudaGetSymbolAddress((void**)&Q,   d_Q);
    cudaGetSymbolAddress((void**)&K,   d_K);
    cudaGetSymbolAddress((void**)&V,   d_V);
    cudaGetSymbolAddress((void**)&G,   d_G);
    cudaGetSymbolAddress((void**)&Y,   d_Y);
    cudaGetSymbolAddress((void**)&X2,  d_X2);
    cudaGetSymbolAddress((void**)&h1,  d_h1);
    cudaGetSymbolAddress((void**)&Sc,  d_Sc);
    cudaGetSymbolAddress((void**)&xpt, d_xpt);

    cudaFuncSetAttribute(tcgemm, cudaFuncAttributeMaxDynamicSharedMemorySize, SMEM_TC);

    layernorm_k<<<NT_, 256>>>(X, ln1_w, ln1_b, Xn);

    // projections
    tcgemm<<<dim3(1,16,B_*H_), NTHREADS, SMEM_TC>>>(Xn, Wq, Q, nullptr, DK_, D_,
        (long long)S_*D_, (long long)D_*DK_, (long long)S_*DK_, H_, H_, 0, 0);
    tcgemm<<<dim3(1,16,B_*H_), NTHREADS, SMEM_TC>>>(Xn, Wk, K, nullptr, DK_, D_,
        (long long)S_*D_, (long long)D_*DK_, (long long)S_*DK_, H_, H_, 0, 0);
    tcgemm<<<dim3(2,16,B_*H_), NTHREADS, SMEM_TC>>>(Xn, Wv, V, nullptr, DV_, D_,
        (long long)S_*D_, (long long)D_*DV_, (long long)S_*DV_, H_, H_, 0, 0);
    tcgemm<<<dim3(16,32,1), NTHREADS, SMEM_TC>>>(Xn, W_G, G, nullptr, VD_, D_,
        0, 0, 0, 1, 1, 0, 0);

    // xpos rotary
    xpos_table_k<<<(S_*64+255)/256, 256>>>(xpt);
    xpos_apply_k<<<(B_*H_*S_*64)/256, 256>>>(Q, K, xpt);

    // retention: scores = Q K^T (K used as B^T) with fused decay; Y = Sc V
    tcgemm<<<dim3(16,16,B_*H_), NTHREADS, SMEM_TC>>>(Q, K, Sc, nullptr, S_, DK_,
        (long long)S_*DK_, (long long)S_*DK_, (long long)S_*S_, 1, B_*H_, 1, 1);
    tcgemm<<<dim3(2,16,B_*H_), NTHREADS, SMEM_TC>>>(Sc, V, Y, nullptr, DV_, S_,
        (long long)S_*S_, (long long)S_*DV_, (long long)S_*DV_, 1, B_*H_, 2, 0);

    // groupnorm + silu gate (in place into G)
    gnorm_gate_k<<<B_*S_*H_, 256>>>(Y, G, gn_w, gn_b);

    // output projection + residual
    tcgemm<<<dim3(8,32,1), NTHREADS, SMEM_TC>>>(G, W_O, X2, nullptr, D_, VD_,
        0, 0, 0, 1, 1, 0, 0);
    add_k<<<(NT_*D_)/256, 256>>>(X2, X, (size_t)NT_*D_);

    // ln2 + FFN
    layernorm_k<<<NT_, 256>>>(X2, ln2_w, ln2_b, Xn);
    tcgemm<<<dim3(32,32,1), NTHREADS, SMEM_TC>>>(Xn, ffn_w1, h1, ffn_b1, FFN_, D_,
        0, 0, 0, 1, 1, 3, 0);
    tcgemm<<<dim3(8,32,1), NTHREADS, SMEM_TC>>>(h1, ffn_w2, out, nullptr, D_, FFN_,
        0, 0, 0, 1, 1, 0, 0);
    final_k<<<(NT_*D_)/256, 256>>>(out, ffn_b2, X2);
}

// round 6
// speedup vs baseline: 3.0010x; 1.3501x over previous
#include <cuda_runtime.h>
#include <cuda_bf16.h>
#include <math.h>

#define B_   2
#define S_   2048
#define D_   1024
#define H_   8
#define FFN_ 4096
#define DK_  128
#define VD_  2048
#define DV_  256
#define NT_  (B_*S_)
#define BH_  (B_*H_)

#define KC       32
#define TSTRIDE  80
#define TILE_B   (128*TSTRIDE)      // 10240
#define STAGE_B  (4*TILE_B)         // 40960: AH, AL, BH, BL
#define NSTAGE   4
#define SMEM_TC  (NSTAGE*STAGE_B)   // 163840
#define NTHREADS 512

typedef __nv_bfloat16 bf16;

// fp32 scratch
__device__ float d_Qf [BH_*S_*DK_];
__device__ float d_Kf [BH_*S_*DK_];
__device__ float d_Vf [BH_*S_*DV_];
__device__ float d_Gf [NT_*VD_];
__device__ float d_Y  [BH_*S_*DV_];
__device__ float d_X2 [NT_*D_];
__device__ float d_xpt[S_*64*4];
// bf16 hi/lo operand buffers
__device__ bf16 d_Xnh[NT_*D_],        d_Xnl[NT_*D_];
__device__ bf16 d_WqTh[H_*DK_*D_],    d_WqTl[H_*DK_*D_];
__device__ bf16 d_WkTh[H_*DK_*D_],    d_WkTl[H_*DK_*D_];
__device__ bf16 d_WvTh[H_*DV_*D_],    d_WvTl[H_*DV_*D_];
__device__ bf16 d_WGTh[VD_*D_],       d_WGTl[VD_*D_];
__device__ bf16 d_WOTh[D_*VD_],       d_WOTl[D_*VD_];
__device__ bf16 d_W1Th[(size_t)D_*FFN_], d_W1Tl[(size_t)D_*FFN_];
__device__ bf16 d_W2Th[(size_t)D_*FFN_], d_W2Tl[(size_t)D_*FFN_];
__device__ bf16 d_Qh[BH_*S_*DK_],     d_Ql[BH_*S_*DK_];
__device__ bf16 d_Kh[BH_*S_*DK_],     d_Kl[BH_*S_*DK_];
__device__ bf16 d_Vth[BH_*DV_*S_],    d_Vtl[BH_*DV_*S_];
__device__ bf16 d_Sch[(size_t)BH_*S_*S_], d_Scl[(size_t)BH_*S_*S_];
__device__ bf16 d_Gh[NT_*VD_],        d_Gl[NT_*VD_];
__device__ bf16 d_h1h[(size_t)NT_*FFN_], d_h1l[(size_t)NT_*FFN_];

__device__ __forceinline__ unsigned smem_u32(const void* p) {
    unsigned a;
    asm("{ .reg .u64 t; cvta.to.shared.u64 t, %1; cvt.u32.u64 %0, t; }"
        : "=r"(a) : "l"(p));
    return a;
}
__device__ __forceinline__ unsigned pack2(float a, float b) {
    unsigned r;
    asm("cvt.rn.bf16x2.f32 %0, %1, %2;" : "=r"(r) : "f"(b), "f"(a));
    return r;   // low 16 = a
}
__device__ __forceinline__ float blo(unsigned p){ return __uint_as_float(p<<16); }
__device__ __forceinline__ float bhi(unsigned p){ return __uint_as_float(p & 0xffff0000u); }

__device__ __forceinline__ void ldm_x4(unsigned* d, unsigned addr) {
    asm volatile("ldmatrix.sync.aligned.m8n8.x4.shared.b16 {%0,%1,%2,%3}, [%4];"
        : "=r"(d[0]), "=r"(d[1]), "=r"(d[2]), "=r"(d[3]) : "r"(addr));
}
__device__ __forceinline__ void mma16816(float* c, const unsigned* a, const unsigned* b) {
    asm volatile("mma.sync.aligned.m16n8k16.row.col.f32.bf16.bf16.f32 "
        "{%0,%1,%2,%3}, {%4,%5,%6,%7}, {%8,%9}, {%0,%1,%2,%3};"
        : "+f"(c[0]), "+f"(c[1]), "+f"(c[2]), "+f"(c[3])
        : "r"(a[0]), "r"(a[1]), "r"(a[2]), "r"(a[3]), "r"(b[0]), "r"(b[1]));
}
__device__ __forceinline__ void cpa16(unsigned dst, const void* src) {
    asm volatile("cp.async.cg.shared.global [%0], [%1], 16;" :: "r"(dst), "l"(src));
}
#define CP_COMMIT() asm volatile("cp.async.commit_group;" ::: "memory")
#define CP_WAIT2()  asm volatile("cp.async.wait_group 2;" ::: "memory")

// ================= pure-async tensor-core GEMM =============================
// C[z] = A[z/aDiv] * B[z%bMod].  A (hi/lo bf16) row-major [M,K];
// B (hi/lo bf16) pre-transposed row-major [N,K].
// mode 0: fp32 out. 1: scores (causal tile skip + decay, split bf16 out).
// 2: retV (K limited to (by+1)*128, fp32 out). 3: bias+GELU, split bf16 out.
__global__ __launch_bounds__(NTHREADS, 1)
void tcgemm(const bf16* __restrict__ AH, const bf16* __restrict__ AL,
            const bf16* __restrict__ BH, const bf16* __restrict__ BL,
            void* __restrict__ Cv, void* __restrict__ C2v,
            const float* __restrict__ bias,
            int N, int K, long long sA, long long sB, long long sC,
            int aDiv, int bMod, int mode)
{
    int bx = blockIdx.x, by = blockIdx.y, bz = blockIdx.z;
    if (mode == 1 && bx > by) return;

    long long ao = (long long)(bz / aDiv) * sA;
    long long bo = (long long)(bz % bMod) * sB;
    AH += ao; AL += ao; BH += bo; BL += bo;

    int Kuse = (mode == 2) ? min(K, (by + 1) * 128) : K;
    int nch  = Kuse >> 5;

    extern __shared__ char smem[];
    unsigned sbase = smem_u32(smem);
    int tid = threadIdx.x, wid = tid >> 5, lane = tid & 31;

    // cp.async mapping: thread -> (row, 16B chunk)
    int crow = tid >> 2, cch = tid & 3;
    const bf16* gA = AH + (long long)(by * 128 + crow) * K + cch * 8;
    const bf16* gAl= AL + (long long)(by * 128 + crow) * K + cch * 8;
    const bf16* gB = BH + (long long)(bx * 128 + crow) * K + cch * 8;
    const bf16* gBl= BL + (long long)(bx * 128 + crow) * K + cch * 8;
    unsigned cdst = (unsigned)crow * TSTRIDE + (unsigned)cch * 16;

    int wm = (wid >> 2) * 32;
    int wn = (wid & 3) * 32;
    float acc[2][4][4];
    #pragma unroll
    for (int i = 0; i < 2; i++)
        #pragma unroll
        for (int j = 0; j < 4; j++)
            #pragma unroll
            for (int p = 0; p < 4; p++) acc[i][j][p] = 0.f;

    unsigned a_off = (unsigned)((lane & 15) * TSTRIDE + ((lane >> 4) << 4));
    unsigned b_off = (unsigned)(((lane & 7) + ((lane >> 4) << 3)) * TSTRIDE
                                + (((lane >> 3) & 1) << 4));

    // prologue: stages 0..2
    #pragma unroll
    for (int s = 0; s < NSTAGE - 1; s++) {
        if (s < nch) {
            unsigned d = sbase + (unsigned)s * STAGE_B + cdst;
            long long ko = (long long)s * KC;
            cpa16(d,             gA  + ko);
            cpa16(d +   TILE_B,  gAl + ko);
            cpa16(d + 2*TILE_B,  gB  + ko);
            cpa16(d + 3*TILE_B,  gBl + ko);
        }
        CP_COMMIT();
    }

    for (int c = 0; c < nch; c++) {
        CP_WAIT2();
        __syncthreads();
        int pf = c + NSTAGE - 1;
        if (pf < nch) {
            unsigned d = sbase + (unsigned)(pf & (NSTAGE-1)) * STAGE_B + cdst;
            long long ko = (long long)pf * KC;
            cpa16(d,             gA  + ko);
            cpa16(d +   TILE_B,  gAl + ko);
            cpa16(d + 2*TILE_B,  gB  + ko);
            cpa16(d + 3*TILE_B,  gBl + ko);
        }
        CP_COMMIT();

        unsigned sb = sbase + (unsigned)(c & (NSTAGE-1)) * STAGE_B;
        #pragma unroll
        for (int ks = 0; ks < 2; ks++) {
            unsigned kb = (unsigned)ks * 32;
            unsigned ah[2][4], al[2][4], bb[2][4];
            #pragma unroll
            for (int mt = 0; mt < 2; mt++)
                ldm_x4(ah[mt], sb + (unsigned)(wm + mt*16) * TSTRIDE + a_off + kb);
            #pragma unroll
            for (int p = 0; p < 2; p++)
                ldm_x4(bb[p], sb + 2*TILE_B + (unsigned)(wn + p*16) * TSTRIDE + b_off + kb);
            #pragma unroll
            for (int mt = 0; mt < 2; mt++)
                #pragma unroll
                for (int nt = 0; nt < 4; nt++)
                    mma16816(acc[mt][nt], ah[mt], &bb[nt>>1][(nt&1)*2]);
            #pragma unroll
            for (int mt = 0; mt < 2; mt++)
                ldm_x4(al[mt], sb + TILE_B + (unsigned)(wm + mt*16) * TSTRIDE + a_off + kb);
            #pragma unroll
            for (int mt = 0; mt < 2; mt++)
                #pragma unroll
                for (int nt = 0; nt < 4; nt++)
                    mma16816(acc[mt][nt], al[mt], &bb[nt>>1][(nt&1)*2]);
            #pragma unroll
            for (int p = 0; p < 2; p++)
                ldm_x4(bb[p], sb + 3*TILE_B + (unsigned)(wn + p*16) * TSTRIDE + b_off + kb);
            #pragma unroll
            for (int mt = 0; mt < 2; mt++)
                #pragma unroll
                for (int nt = 0; nt < 4; nt++)
                    mma16816(acc[mt][nt], ah[mt], &bb[nt>>1][(nt&1)*2]);
        }
    }

    // ---------------- epilogue ----------------
    float lg2g = 0.f;
    if (mode == 1) {
        const float l32 = -3.4657359027997265f, l512 = -6.2383246250395075f;
        float g = 1.0f - expf(l32 + (l512 - l32) * (float)(bz & (H_-1)) * (1.0f/7.0f));
        lg2g = log2f(g);
    }
    bool split = (mode == 1 || mode == 3);
    float* Cf = (float*)Cv + (long long)bz * (split ? 0 : sC);
    unsigned short* Ch = (unsigned short*)Cv  + (long long)bz * (split ? sC : 0);
    unsigned short* Cl = (unsigned short*)C2v + (long long)bz * (split ? sC : 0);

    int rbase = by * 128 + wm + (lane >> 2);
    int cbase = bx * 128 + wn + (lane & 3) * 2;
    #pragma unroll
    for (int mt = 0; mt < 2; mt++) {
        #pragma unroll
        for (int half = 0; half < 2; half++) {
            int grow = rbase + mt*16 + half*8;
            #pragma unroll
            for (int nt = 0; nt < 4; nt++) {
                float v0 = acc[mt][nt][half*2], v1 = acc[mt][nt][half*2+1];
                int gcol = cbase + nt*8;
                if (mode == 1) {
                    int d0 = grow - gcol, d1 = d0 - 1;
                    v0 = (d0 >= 0) ? v0 * exp2f((float)d0 * lg2g) : 0.f;
                    v1 = (d1 >= 0) ? v1 * exp2f((float)d1 * lg2g) : 0.f;
                } else if (mode == 3) {
                    float x0 = v0 + bias[gcol], x1 = v1 + bias[gcol+1];
                    v0 = 0.5f*x0*(1.0f + erff(x0*0.70710678118654752f));
                    v1 = 0.5f*x1*(1.0f + erff(x1*0.70710678118654752f));
                }
                if (split) {
                    unsigned hp = pack2(v0, v1);
                    unsigned lp = pack2(v0 - blo(hp), v1 - bhi(hp));
                    *(unsigned*)(Ch + (long long)grow * N + gcol) = hp;
                    *(unsigned*)(Cl + (long long)grow * N + gcol) = lp;
                } else {
                    *(float2*)(Cf + (long long)grow * N + gcol) = make_float2(v0, v1);
                }
            }
        }
    }
}

// ================= pre/post kernels =========================================
template<int NT>
__device__ __forceinline__ float blockSum(float v) {
    __shared__ float sh[NT/32];
    int lane = threadIdx.x & 31, w = threadIdx.x >> 5;
    #pragma unroll
    for (int o = 16; o > 0; o >>= 1) v += __shfl_xor_sync(0xffffffffu, v, o);
    if (lane == 0) sh[w] = v;
    __syncthreads();
    float t = 0.f;
    #pragma unroll
    for (int i = 0; i < NT/32; i++) t += sh[i];
    __syncthreads();
    return t;
}

// transpose + split: in [K,N] fp32 (batched) -> out [N,K] bf16 hi/lo
__global__ void wsplit_t(const float* __restrict__ W,
                         bf16* __restrict__ Th, bf16* __restrict__ Tl,
                         int K, int N)
{
    __shared__ float t[32][33];
    long long zo = (long long)blockIdx.z * K * N;
    int k0 = blockIdx.x*32, n0 = blockIdx.y*32;
    int tx = threadIdx.x, ty = threadIdx.y;
    #pragma unroll
    for (int j = 0; j < 32; j += 8)
        t[ty+j][tx] = W[zo + (long long)(k0+ty+j)*N + n0+tx];
    __syncthreads();
    #pragma unroll
    for (int j = 0; j < 32; j += 8) {
        float v = t[tx][ty+j];
        long long o = zo + (long long)(n0+ty+j)*K + k0+tx;
        bf16 h = __float2bfloat16(v);
        Th[o] = h;
        Tl[o] = __float2bfloat16(v - __bfloat162float(h));
    }
}

__global__ void layernorm_split(const float* __restrict__ X,
                                const float* __restrict__ w, const float* __restrict__ b,
                                bf16* __restrict__ oh, bf16* __restrict__ ol)
{
    size_t tok = blockIdx.x;
    const float* x = X + tok * D_;
    int t2 = threadIdx.x * 2;
    float2 p0 = *(const float2*)(x + t2);
    float2 p1 = *(const float2*)(x + t2 + 512);
    float s = p0.x + p0.y + p1.x + p1.y;
    float mean = blockSum<256>(s) * (1.0f / D_);
    float d0 = p0.x-mean, d1 = p0.y-mean, d2 = p1.x-mean, d3 = p1.y-mean;
    float var = blockSum<256>(d0*d0 + d1*d1 + d2*d2 + d3*d3) * (1.0f / D_);
    float inv = rsqrtf(var + 1e-5f);
    float o0 = d0*inv*w[t2]     + b[t2];
    float o1 = d1*inv*w[t2+1]   + b[t2+1];
    float o2 = d2*inv*w[t2+512] + b[t2+512];
    float o3 = d3*inv*w[t2+513] + b[t2+513];
    unsigned hp0 = pack2(o0,o1), hp1 = pack2(o2,o3);
    *(unsigned*)(oh + tok*D_ + t2)       = hp0;
    *(unsigned*)(oh + tok*D_ + t2 + 512) = hp1;
    *(unsigned*)(ol + tok*D_ + t2)       = pack2(o0-blo(hp0), o1-bhi(hp0));
    *(unsigned*)(ol + tok*D_ + t2 + 512) = pack2(o2-blo(hp1), o3-bhi(hp1));
}

__global__ void xpos_table_k(float* __restrict__ tab)
{
    int idx = blockIdx.x * 256 + threadIdx.x;
    if (idx >= S_ * 64) return;
    int i = idx & 63, s = idx >> 6;
    double scl = pow((2.0*i + 51.2) / 179.2, (double)s / 512.0);
    float ang_f = (float)s * (float)pow(10000.0, -(double)i / 64.0);
    double sn = sin((double)ang_f), cs = cos((double)ang_f);
    tab[idx*4+0] = (float)(cs * scl);  tab[idx*4+1] = (float)(sn * scl);
    tab[idx*4+2] = (float)(cs / scl);  tab[idx*4+3] = (float)(sn / scl);
}

__global__ void xpos_split(const float* __restrict__ Qf, const float* __restrict__ Kf,
                           const float* __restrict__ tab,
                           bf16* __restrict__ Qh, bf16* __restrict__ Ql,
                           bf16* __restrict__ Kh, bf16* __restrict__ Kl)
{
    long long idx = (long long)blockIdx.x * 256 + threadIdx.x;
    if (idx >= (long long)BH_*S_*64) return;
    int i = (int)(idx & 63);
    long long rr = idx >> 6;
    int s = (int)(rr % S_);
    long long base = rr * 128 + 2*i;
    const float* t = tab + ((long long)s*64 + i) * 4;
    float q1 = Qf[base], q2 = Qf[base+1];
    float o0 = q1*t[0] - q2*t[1];
    float o1 = q2*t[0] + q1*t[1];
    unsigned hp = pack2(o0, o1);
    *(unsigned*)(Qh + base) = hp;
    *(unsigned*)(Ql + base) = pack2(o0-blo(hp), o1-bhi(hp));
    float k1 = Kf[base], k2 = Kf[base+1];
    o0 = k1*t[2] - k2*t[3];
    o1 = k2*t[2] + k1*t[3];
    hp = pack2(o0, o1);
    *(unsigned*)(Kh + base) = hp;
    *(unsigned*)(Kl + base) = pack2(o0-blo(hp), o1-bhi(hp));
}

__global__ void gnorm_gate_split(const float* __restrict__ Y, const float* __restrict__ G,
                                 const float* __restrict__ w, const float* __restrict__ bb,
                                 bf16* __restrict__ oh, bf16* __restrict__ ol)
{
    int h = blockIdx.x % H_, s = (blockIdx.x / H_) % S_, b = blockIdx.x / (H_*S_);
    int v = threadIdx.x;
    size_t yoff = (((size_t)(b*H_+h))*S_ + s)*DV_ + v;
    float y = Y[yoff];
    float mean = blockSum<256>(y) * (1.0f/DV_);
    float d = y - mean;
    float yn = d * rsqrtf(blockSum<256>(d*d)*(1.0f/DV_) + 1e-5f);
    int col = h*DV_ + v;
    size_t goff = ((size_t)(b*S_+s))*VD_ + col;
    float g = G[goff];
    float val = (g / (1.0f + expf(-g))) * (yn * w[col] + bb[col]);
    bf16 hh = __float2bfloat16(val);
    oh[goff] = hh;
    ol[goff] = __float2bfloat16(val - __bfloat162float(hh));
}

__global__ void add_k(float* __restrict__ a, const float* __restrict__ b, size_t n)
{
    size_t i = (size_t)blockIdx.x * 256 + threadIdx.x;
    if (i < n) a[i] += b[i];
}

__global__ void final_k(float* __restrict__ out, const float* __restrict__ b2,
                        const float* __restrict__ X2)
{
    size_t i = (size_t)blockIdx.x * 256 + threadIdx.x;
    if (i >= (size_t)NT_ * D_) return;
    out[i] = out[i] + b2[i & (D_-1)] + X2[i];
}

// ================= host launcher ============================================
extern "C" void kernel_launch(void* const* d_in, const int* in_sizes, int n_in,
                              void* d_out, int out_size)
{
    (void)in_sizes; (void)n_in; (void)out_size;
    const float* X      = (const float*)d_in[0];
    const float* Wq     = (const float*)d_in[1];
    const float* Wk     = (const float*)d_in[2];
    const float* Wv     = (const float*)d_in[3];
    const float* W_G    = (const float*)d_in[4];
    const float* W_O    = (const float*)d_in[5];
    const float* gn_w   = (const float*)d_in[6];
    const float* gn_b   = (const float*)d_in[7];
    const float* ln1_w  = (const float*)d_in[8];
    const float* ln1_b  = (const float*)d_in[9];
    const float* ln2_w  = (const float*)d_in[10];
    const float* ln2_b  = (const float*)d_in[11];
    const float* ffn_w1 = (const float*)d_in[12];
    const float* ffn_b1 = (const float*)d_in[13];
    const float* ffn_w2 = (const float*)d_in[14];
    const float* ffn_b2 = (const float*)d_in[15];
    float* out = (float*)d_out;

    float *Qf,*Kf,*Vf,*Gf,*Y,*X2,*xpt;
    bf16 *Xnh,*Xnl,*WqTh,*WqTl,*WkTh,*WkTl,*WvTh,*WvTl,*WGTh,*WGTl,*WOTh,*WOTl;
    bf16 *W1Th,*W1Tl,*W2Th,*W2Tl,*Qh,*Ql,*Kh,*Kl,*Vth,*Vtl,*Sch,*Scl,*Gh,*Gl,*h1h,*h1l;
    cudaGetSymbolAddress((void**)&Qf,  d_Qf);   cudaGetSymbolAddress((void**)&Kf,  d_Kf);
    cudaGetSymbolAddress((void**)&Vf,  d_Vf);   cudaGetSymbolAddress((void**)&Gf,  d_Gf);
    cudaGetSymbolAddress((void**)&Y,   d_Y);    cudaGetSymbolAddress((void**)&X2,  d_X2);
    cudaGetSymbolAddress((void**)&xpt, d_xpt);
    cudaGetSymbolAddress((void**)&Xnh, d_Xnh);  cudaGetSymbolAddress((void**)&Xnl, d_Xnl);
    cudaGetSymbolAddress((void**)&WqTh,d_WqTh); cudaGetSymbolAddress((void**)&WqTl,d_WqTl);
    cudaGetSymbolAddress((void**)&WkTh,d_WkTh); cudaGetSymbolAddress((void**)&WkTl,d_WkTl);
    cudaGetSymbolAddress((void**)&WvTh,d_WvTh); cudaGetSymbolAddress((void**)&WvTl,d_WvTl);
    cudaGetSymbolAddress((void**)&WGTh,d_WGTh); cudaGetSymbolAddress((void**)&WGTl,d_WGTl);
    cudaGetSymbolAddress((void**)&WOTh,d_WOTh); cudaGetSymbolAddress((void**)&WOTl,d_WOTl);
    cudaGetSymbolAddress((void**)&W1Th,d_W1Th); cudaGetSymbolAddress((void**)&W1Tl,d_W1Tl);
    cudaGetSymbolAddress((void**)&W2Th,d_W2Th); cudaGetSymbolAddress((void**)&W2Tl,d_W2Tl);
    cudaGetSymbolAddress((void**)&Qh,  d_Qh);   cudaGetSymbolAddress((void**)&Ql,  d_Ql);
    cudaGetSymbolAddress((void**)&Kh,  d_Kh);   cudaGetSymbolAddress((void**)&Kl,  d_Kl);
    cudaGetSymbolAddress((void**)&Vth, d_Vth);  cudaGetSymbolAddress((void**)&Vtl, d_Vtl);
    cudaGetSymbolAddress((void**)&Sch, d_Sch);  cudaGetSymbolAddress((void**)&Scl, d_Scl);
    cudaGetSymbolAddress((void**)&Gh,  d_Gh);   cudaGetSymbolAddress((void**)&Gl,  d_Gl);
    cudaGetSymbolAddress((void**)&h1h, d_h1h);  cudaGetSymbolAddress((void**)&h1l, d_h1l);

    cudaFuncSetAttribute(tcgemm, cudaFuncAttributeMaxDynamicSharedMemorySize, SMEM_TC);
    dim3 tb(32, 8);

    // weight transpose + split
    wsplit_t<<<dim3(D_/32,  DK_/32,  H_), tb>>>(Wq,     WqTh, WqTl, D_,  DK_);
    wsplit_t<<<dim3(D_/32,  DK_/32,  H_), tb>>>(Wk,     WkTh, WkTl, D_,  DK_);
    wsplit_t<<<dim3(D_/32,  DV_/32,  H_), tb>>>(Wv,     WvTh, WvTl, D_,  DV_);
    wsplit_t<<<dim3(D_/32,  VD_/32,  1),  tb>>>(W_G,    WGTh, WGTl, D_,  VD_);
    wsplit_t<<<dim3(VD_/32, D_/32,   1),  tb>>>(W_O,    WOTh, WOTl, VD_, D_);
    wsplit_t<<<dim3(D_/32,  FFN_/32, 1),  tb>>>(ffn_w1, W1Th, W1Tl, D_,  FFN_);
    wsplit_t<<<dim3(FFN_/32, D_/32,  1),  tb>>>(ffn_w2, W2Th, W2Tl, FFN_, D_);

    // ln1
    layernorm_split<<<NT_, 256>>>(X, ln1_w, ln1_b, Xnh, Xnl);

    // projections (fp32 outputs)
    tcgemm<<<dim3(1,16,BH_), NTHREADS, SMEM_TC>>>(Xnh, Xnl, WqTh, WqTl, Qf, nullptr,
        nullptr, DK_, D_, (long long)S_*D_, (long long)DK_*D_, (long long)S_*DK_, H_, H_, 0);
    tcgemm<<<dim3(1,16,BH_), NTHREADS, SMEM_TC>>>(Xnh, Xnl, WkTh, WkTl, Kf, nullptr,
        nullptr, DK_, D_, (long long)S_*D_, (long long)DK_*D_, (long long)S_*DK_, H_, H_, 0);
    tcgemm<<<dim3(2,16,BH_), NTHREADS, SMEM_TC>>>(Xnh, Xnl, WvTh, WvTl, Vf, nullptr,
        nullptr, DV_, D_, (long long)S_*D_, (long long)DV_*D_, (long long)S_*DV_, H_, H_, 0);
    tcgemm<<<dim3(16,32,1), NTHREADS, SMEM_TC>>>(Xnh, Xnl, WGTh, WGTl, Gf, nullptr,
        nullptr, VD_, D_, 0, 0, 0, 1, 1, 0);

    // xpos rotary -> split Q/K; V transpose+split
    xpos_table_k<<<(S_*64+255)/256, 256>>>(xpt);
    xpos_split<<<(BH_*S_*64)/256, 256>>>(Qf, Kf, xpt, Qh, Ql, Kh, Kl);
    wsplit_t<<<dim3(S_/32, DV_/32, BH_), tb>>>(Vf, Vth, Vtl, S_, DV_);

    // scores = Q K^T (fused causal decay, split bf16 out)
    tcgemm<<<dim3(16,16,BH_), NTHREADS, SMEM_TC>>>(Qh, Ql, Kh, Kl, Sch, Scl,
        nullptr, S_, DK_, (long long)S_*DK_, (long long)S_*DK_, (long long)S_*S_, 1, BH_, 1);
    // Y = Sc V  (K-limited)
    tcgemm<<<dim3(2,16,BH_), NTHREADS, SMEM_TC>>>(Sch, Scl, Vth, Vtl, Y, nullptr,
        nullptr, DV_, S_, (long long)S_*S_, (long long)DV_*S_, (long long)S_*DV_, 1, BH_, 2);

    // groupnorm + gate -> split
    gnorm_gate_split<<<B_*S_*H_, 256>>>(Y, Gf, gn_w, gn_b, Gh, Gl);

    // output projection + residual
    tcgemm<<<dim3(8,32,1), NTHREADS, SMEM_TC>>>(Gh, Gl, WOTh, WOTl, X2, nullptr,
        nullptr, D_, VD_, 0, 0, 0, 1, 1, 0);
    add_k<<<(NT_*D_)/256, 256>>>(X2, X, (size_t)NT_*D_);

    // ln2 + FFN
    layernorm_split<<<NT_, 256>>>(X2, ln2_w, ln2_b, Xnh, Xnl);
    tcgemm<<<dim3(32,32,1), NTHREADS, SMEM_TC>>>(Xnh, Xnl, W1Th, W1Tl, h1h, h1l,
        ffn_b1, FFN_, D_, 0, 0, 0, 1, 1, 3);
    tcgemm<<<dim3(8,32,1), NTHREADS, SMEM_TC>>>(h1h, h1l, W2Th, W2Tl, out, nullptr,
        nullptr, D_, FFN_, 0, 0, 0, 1, 1, 0);
    final_k<<<(NT_*D_)/256, 256>>>(out, ffn_b2, X2);
}

// round 7
// speedup vs baseline: 3.0651x; 1.0213x over previous
#include <cuda_runtime.h>
#include <cuda_bf16.h>
#include <math.h>

#define B_   2
#define S_   2048
#define D_   1024
#define H_   8
#define FFN_ 4096
#define DK_  128
#define VD_  2048
#define DV_  256
#define NT_  (B_*S_)
#define BH_  (B_*H_)

#define KC       32
#define TSTRIDE  80
#define TILE_B   (128*TSTRIDE)      // 10240
#define STAGE_B  (4*TILE_B)         // 40960: AH, AL, BH, BL
#define NSTAGE   2
#define SMEM_TC  (NSTAGE*STAGE_B)   // 81920
#define NTHREADS 256

typedef __nv_bfloat16 bf16;

// fp32 scratch
__device__ float d_Qf [BH_*S_*DK_];
__device__ float d_Kf [BH_*S_*DK_];
__device__ float d_Vf [BH_*S_*DV_];
__device__ float d_Gf [NT_*VD_];
__device__ float d_Y  [BH_*S_*DV_];
__device__ float d_X2 [NT_*D_];
__device__ float d_xpt[S_*64*4];
// bf16 hi/lo operand buffers
__device__ bf16 d_Xnh[NT_*D_],        d_Xnl[NT_*D_];
__device__ bf16 d_WqTh[H_*DK_*D_],    d_WqTl[H_*DK_*D_];
__device__ bf16 d_WkTh[H_*DK_*D_],    d_WkTl[H_*DK_*D_];
__device__ bf16 d_WvTh[H_*DV_*D_],    d_WvTl[H_*DV_*D_];
__device__ bf16 d_WGTh[VD_*D_],       d_WGTl[VD_*D_];
__device__ bf16 d_WOTh[D_*VD_],       d_WOTl[D_*VD_];
__device__ bf16 d_W1Th[(size_t)D_*FFN_], d_W1Tl[(size_t)D_*FFN_];
__device__ bf16 d_W2Th[(size_t)D_*FFN_], d_W2Tl[(size_t)D_*FFN_];
__device__ bf16 d_Qh[BH_*S_*DK_],     d_Ql[BH_*S_*DK_];
__device__ bf16 d_Kh[BH_*S_*DK_],     d_Kl[BH_*S_*DK_];
__device__ bf16 d_Vth[BH_*DV_*S_],    d_Vtl[BH_*DV_*S_];
__device__ bf16 d_Sch[(size_t)BH_*S_*S_], d_Scl[(size_t)BH_*S_*S_];
__device__ bf16 d_Gh[NT_*VD_],        d_Gl[NT_*VD_];
__device__ bf16 d_h1h[(size_t)NT_*FFN_], d_h1l[(size_t)NT_*FFN_];

__device__ __forceinline__ unsigned smem_u32(const void* p) {
    unsigned a;
    asm("{ .reg .u64 t; cvta.to.shared.u64 t, %1; cvt.u32.u64 %0, t; }"
        : "=r"(a) : "l"(p));
    return a;
}
__device__ __forceinline__ unsigned pack2(float a, float b) {
    unsigned r;
    asm("cvt.rn.bf16x2.f32 %0, %1, %2;" : "=r"(r) : "f"(b), "f"(a));
    return r;   // low 16 = a
}
__device__ __forceinline__ float blo(unsigned p){ return __uint_as_float(p<<16); }
__device__ __forceinline__ float bhi(unsigned p){ return __uint_as_float(p & 0xffff0000u); }

__device__ __forceinline__ void ldm_x4(unsigned* d, unsigned addr) {
    asm volatile("ldmatrix.sync.aligned.m8n8.x4.shared.b16 {%0,%1,%2,%3}, [%4];"
        : "=r"(d[0]), "=r"(d[1]), "=r"(d[2]), "=r"(d[3]) : "r"(addr));
}
__device__ __forceinline__ void mma16816(float* c, const unsigned* a, const unsigned* b) {
    asm volatile("mma.sync.aligned.m16n8k16.row.col.f32.bf16.bf16.f32 "
        "{%0,%1,%2,%3}, {%4,%5,%6,%7}, {%8,%9}, {%0,%1,%2,%3};"
        : "+f"(c[0]), "+f"(c[1]), "+f"(c[2]), "+f"(c[3])
        : "r"(a[0]), "r"(a[1]), "r"(a[2]), "r"(a[3]), "r"(b[0]), "r"(b[1]));
}
__device__ __forceinline__ void cpa16(unsigned dst, const void* src) {
    asm volatile("cp.async.cg.shared.global [%0], [%1], 16;" :: "r"(dst), "l"(src));
}
#define CP_COMMIT() asm volatile("cp.async.commit_group;" ::: "memory")
#define CP_WAIT0()  asm volatile("cp.async.wait_group 0;" ::: "memory")

// ================= async tensor-core GEMM (256 thr, 2 CTAs/SM) =============
// C[z] = A[z/aDiv] * B[z%bMod].  A (hi/lo bf16) row-major [M,K];
// B (hi/lo bf16) pre-transposed row-major [N,K].
// mode 0: fp32 out. 1: scores (causal tile skip + decay, split bf16 out).
// 2: retV (K limited to (by+1)*128, fp32 out). 3: bias+GELU, split bf16 out.
__global__ __launch_bounds__(NTHREADS, 2)
void tcgemm(const bf16* __restrict__ AH, const bf16* __restrict__ AL,
            const bf16* __restrict__ BH, const bf16* __restrict__ BL,
            void* __restrict__ Cv, void* __restrict__ C2v,
            const float* __restrict__ bias,
            int N, int K, long long sA, long long sB, long long sC,
            int aDiv, int bMod, int mode)
{
    int bx = blockIdx.x, by = blockIdx.y, bz = blockIdx.z;
    if (mode == 1 && bx > by) return;

    long long ao = (long long)(bz / aDiv) * sA;
    long long bo = (long long)(bz % bMod) * sB;
    AH += ao; AL += ao; BH += bo; BL += bo;

    int Kuse = (mode == 2) ? min(K, (by + 1) * 128) : K;
    int nch  = Kuse >> 5;

    extern __shared__ char smem[];
    unsigned sbase = smem_u32(smem);
    int tid = threadIdx.x, wid = tid >> 5, lane = tid & 31;

    // cp.async mapping: thread -> (row, two 16B chunks)
    int crow = tid >> 1, cch = (tid & 1) * 2;
    const bf16* gA = AH + (long long)(by * 128 + crow) * K + cch * 8;
    const bf16* gAl= AL + (long long)(by * 128 + crow) * K + cch * 8;
    const bf16* gB = BH + (long long)(bx * 128 + crow) * K + cch * 8;
    const bf16* gBl= BL + (long long)(bx * 128 + crow) * K + cch * 8;
    unsigned cdst = (unsigned)crow * TSTRIDE + (unsigned)cch * 16;

    int wm = (wid >> 1) * 32;     // warp m offset (4 rows of warps)
    int wn = (wid & 1) * 64;      // warp n offset (2 cols of warps)
    float acc[2][8][4];
    #pragma unroll
    for (int i = 0; i < 2; i++)
        #pragma unroll
        for (int j = 0; j < 8; j++)
            #pragma unroll
            for (int p = 0; p < 4; p++) acc[i][j][p] = 0.f;

    unsigned a_off = (unsigned)((lane & 15) * TSTRIDE + ((lane >> 4) << 4));
    unsigned b_off = (unsigned)(((lane & 7) + ((lane >> 4) << 3)) * TSTRIDE
                                + (((lane >> 3) & 1) << 4));

    auto prefetch = [&](int s, int stage) {
        unsigned d = sbase + (unsigned)stage * STAGE_B + cdst;
        long long ko = (long long)s * KC;
        cpa16(d,                  gA  + ko);
        cpa16(d + 16,             gA  + ko + 8);
        cpa16(d +   TILE_B,       gAl + ko);
        cpa16(d +   TILE_B + 16,  gAl + ko + 8);
        cpa16(d + 2*TILE_B,       gB  + ko);
        cpa16(d + 2*TILE_B + 16,  gB  + ko + 8);
        cpa16(d + 3*TILE_B,       gBl + ko);
        cpa16(d + 3*TILE_B + 16,  gBl + ko + 8);
    };

    prefetch(0, 0);
    CP_COMMIT();

    for (int c = 0; c < nch; c++) {
        CP_WAIT0();
        __syncthreads();
        if (c + 1 < nch) prefetch(c + 1, (c + 1) & 1);
        CP_COMMIT();

        unsigned sb = sbase + (unsigned)(c & 1) * STAGE_B;
        #pragma unroll
        for (int ks = 0; ks < 2; ks++) {
            unsigned kb = (unsigned)ks * 32;
            unsigned ah[2][4], al[2][4], bb[4][4];
            #pragma unroll
            for (int mt = 0; mt < 2; mt++)
                ldm_x4(ah[mt], sb + (unsigned)(wm + mt*16) * TSTRIDE + a_off + kb);
            #pragma unroll
            for (int p = 0; p < 4; p++)
                ldm_x4(bb[p], sb + 2*TILE_B + (unsigned)(wn + p*16) * TSTRIDE + b_off + kb);
            #pragma unroll
            for (int mt = 0; mt < 2; mt++)
                #pragma unroll
                for (int nt = 0; nt < 8; nt++)
                    mma16816(acc[mt][nt], ah[mt], &bb[nt>>1][(nt&1)*2]);
            #pragma unroll
            for (int mt = 0; mt < 2; mt++)
                ldm_x4(al[mt], sb + TILE_B + (unsigned)(wm + mt*16) * TSTRIDE + a_off + kb);
            #pragma unroll
            for (int mt = 0; mt < 2; mt++)
                #pragma unroll
                for (int nt = 0; nt < 8; nt++)
                    mma16816(acc[mt][nt], al[mt], &bb[nt>>1][(nt&1)*2]);
            #pragma unroll
            for (int p = 0; p < 4; p++)
                ldm_x4(bb[p], sb + 3*TILE_B + (unsigned)(wn + p*16) * TSTRIDE + b_off + kb);
            #pragma unroll
            for (int mt = 0; mt < 2; mt++)
                #pragma unroll
                for (int nt = 0; nt < 8; nt++)
                    mma16816(acc[mt][nt], ah[mt], &bb[nt>>1][(nt&1)*2]);
        }
    }

    // ---------------- epilogue ----------------
    float lg2g = 0.f;
    if (mode == 1) {
        const float l32 = -3.4657359027997265f, l512 = -6.2383246250395075f;
        float g = 1.0f - expf(l32 + (l512 - l32) * (float)(bz & (H_-1)) * (1.0f/7.0f));
        lg2g = log2f(g);
    }
    bool split = (mode == 1 || mode == 3);
    float* Cf = (float*)Cv + (long long)bz * (split ? 0 : sC);
    unsigned short* Ch = (unsigned short*)Cv  + (long long)bz * (split ? sC : 0);
    unsigned short* Cl = (unsigned short*)C2v + (long long)bz * (split ? sC : 0);

    int rbase = by * 128 + wm + (lane >> 2);
    int cbase = bx * 128 + wn + (lane & 3) * 2;
    #pragma unroll
    for (int mt = 0; mt < 2; mt++) {
        #pragma unroll
        for (int half = 0; half < 2; half++) {
            int grow = rbase + mt*16 + half*8;
            #pragma unroll
            for (int nt = 0; nt < 8; nt++) {
                float v0 = acc[mt][nt][half*2], v1 = acc[mt][nt][half*2+1];
                int gcol = cbase + nt*8;
                if (mode == 1) {
                    int d0 = grow - gcol, d1 = d0 - 1;
                    v0 = (d0 >= 0) ? v0 * exp2f((float)d0 * lg2g) : 0.f;
                    v1 = (d1 >= 0) ? v1 * exp2f((float)d1 * lg2g) : 0.f;
                } else if (mode == 3) {
                    float x0 = v0 + bias[gcol], x1 = v1 + bias[gcol+1];
                    v0 = 0.5f*x0*(1.0f + erff(x0*0.70710678118654752f));
                    v1 = 0.5f*x1*(1.0f + erff(x1*0.70710678118654752f));
                }
                if (split) {
                    unsigned hp = pack2(v0, v1);
                    unsigned lp = pack2(v0 - blo(hp), v1 - bhi(hp));
                    *(unsigned*)(Ch + (long long)grow * N + gcol) = hp;
                    *(unsigned*)(Cl + (long long)grow * N + gcol) = lp;
                } else {
                    *(float2*)(Cf + (long long)grow * N + gcol) = make_float2(v0, v1);
                }
            }
        }
    }
}

// ================= pre/post kernels =========================================
template<int NT>
__device__ __forceinline__ float blockSum(float v) {
    __shared__ float sh[NT/32];
    int lane = threadIdx.x & 31, w = threadIdx.x >> 5;
    #pragma unroll
    for (int o = 16; o > 0; o >>= 1) v += __shfl_xor_sync(0xffffffffu, v, o);
    if (lane == 0) sh[w] = v;
    __syncthreads();
    float t = 0.f;
    #pragma unroll
    for (int i = 0; i < NT/32; i++) t += sh[i];
    __syncthreads();
    return t;
}

// transpose + split: in [K,N] fp32 (batched) -> out [N,K] bf16 hi/lo
__global__ void wsplit_t(const float* __restrict__ W,
                         bf16* __restrict__ Th, bf16* __restrict__ Tl,
                         int K, int N)
{
    __shared__ float t[32][33];
    long long zo = (long long)blockIdx.z * K * N;
    int k0 = blockIdx.x*32, n0 = blockIdx.y*32;
    int tx = threadIdx.x, ty = threadIdx.y;
    #pragma unroll
    for (int j = 0; j < 32; j += 8)
        t[ty+j][tx] = W[zo + (long long)(k0+ty+j)*N + n0+tx];
    __syncthreads();
    #pragma unroll
    for (int j = 0; j < 32; j += 8) {
        float v = t[tx][ty+j];
        long long o = zo + (long long)(n0+ty+j)*K + k0+tx;
        bf16 h = __float2bfloat16(v);
        Th[o] = h;
        Tl[o] = __float2bfloat16(v - __bfloat162float(h));
    }
}

__global__ void layernorm_split(const float* __restrict__ X,
                                const float* __restrict__ w, const float* __restrict__ b,
                                bf16* __restrict__ oh, bf16* __restrict__ ol)
{
    size_t tok = blockIdx.x;
    const float* x = X + tok * D_;
    int t2 = threadIdx.x * 2;
    float2 p0 = *(const float2*)(x + t2);
    float2 p1 = *(const float2*)(x + t2 + 512);
    float s = p0.x + p0.y + p1.x + p1.y;
    float mean = blockSum<256>(s) * (1.0f / D_);
    float d0 = p0.x-mean, d1 = p0.y-mean, d2 = p1.x-mean, d3 = p1.y-mean;
    float var = blockSum<256>(d0*d0 + d1*d1 + d2*d2 + d3*d3) * (1.0f / D_);
    float inv = rsqrtf(var + 1e-5f);
    float o0 = d0*inv*w[t2]     + b[t2];
    float o1 = d1*inv*w[t2+1]   + b[t2+1];
    float o2 = d2*inv*w[t2+512] + b[t2+512];
    float o3 = d3*inv*w[t2+513] + b[t2+513];
    unsigned hp0 = pack2(o0,o1), hp1 = pack2(o2,o3);
    *(unsigned*)(oh + tok*D_ + t2)       = hp0;
    *(unsigned*)(oh + tok*D_ + t2 + 512) = hp1;
    *(unsigned*)(ol + tok*D_ + t2)       = pack2(o0-blo(hp0), o1-bhi(hp0));
    *(unsigned*)(ol + tok*D_ + t2 + 512) = pack2(o2-blo(hp1), o3-bhi(hp1));
}

__global__ void xpos_table_k(float* __restrict__ tab)
{
    int idx = blockIdx.x * 256 + threadIdx.x;
    if (idx >= S_ * 64) return;
    int i = idx & 63, s = idx >> 6;
    double scl = pow((2.0*i + 51.2) / 179.2, (double)s / 512.0);
    float ang_f = (float)s * (float)pow(10000.0, -(double)i / 64.0);
    double sn = sin((double)ang_f), cs = cos((double)ang_f);
    tab[idx*4+0] = (float)(cs * scl);  tab[idx*4+1] = (float)(sn * scl);
    tab[idx*4+2] = (float)(cs / scl);  tab[idx*4+3] = (float)(sn / scl);
}

__global__ void xpos_split(const float* __restrict__ Qf, const float* __restrict__ Kf,
                           const float* __restrict__ tab,
                           bf16* __restrict__ Qh, bf16* __restrict__ Ql,
                           bf16* __restrict__ Kh, bf16* __restrict__ Kl)
{
    long long idx = (long long)blockIdx.x * 256 + threadIdx.x;
    if (idx >= (long long)BH_*S_*64) return;
    int i = (int)(idx & 63);
    long long rr = idx >> 6;
    int s = (int)(rr % S_);
    long long base = rr * 128 + 2*i;
    const float* t = tab + ((long long)s*64 + i) * 4;
    float q1 = Qf[base], q2 = Qf[base+1];
    float o0 = q1*t[0] - q2*t[1];
    float o1 = q2*t[0] + q1*t[1];
    unsigned hp = pack2(o0, o1);
    *(unsigned*)(Qh + base) = hp;
    *(unsigned*)(Ql + base) = pack2(o0-blo(hp), o1-bhi(hp));
    float k1 = Kf[base], k2 = Kf[base+1];
    o0 = k1*t[2] - k2*t[3];
    o1 = k2*t[2] + k1*t[3];
    hp = pack2(o0, o1);
    *(unsigned*)(Kh + base) = hp;
    *(unsigned*)(Kl + base) = pack2(o0-blo(hp), o1-bhi(hp));
}

__global__ void gnorm_gate_split(const float* __restrict__ Y, const float* __restrict__ G,
                                 const float* __restrict__ w, const float* __restrict__ bb,
                                 bf16* __restrict__ oh, bf16* __restrict__ ol)
{
    int h = blockIdx.x % H_, s = (blockIdx.x / H_) % S_, b = blockIdx.x / (H_*S_);
    int v = threadIdx.x;
    size_t yoff = (((size_t)(b*H_+h))*S_ + s)*DV_ + v;
    float y = Y[yoff];
    float mean = blockSum<256>(y) * (1.0f/DV_);
    float d = y - mean;
    float yn = d * rsqrtf(blockSum<256>(d*d)*(1.0f/DV_) + 1e-5f);
    int col = h*DV_ + v;
    size_t goff = ((size_t)(b*S_+s))*VD_ + col;
    float g = G[goff];
    float val = (g / (1.0f + expf(-g))) * (yn * w[col] + bb[col]);
    bf16 hh = __float2bfloat16(val);
    oh[goff] = hh;
    ol[goff] = __float2bfloat16(val - __bfloat162float(hh));
}

__global__ void add_k(float* __restrict__ a, const float* __restrict__ b, size_t n)
{
    size_t i = (size_t)blockIdx.x * 256 + threadIdx.x;
    if (i < n) a[i] += b[i];
}

__global__ void final_k(float* __restrict__ out, const float* __restrict__ b2,
                        const float* __restrict__ X2)
{
    size_t i = (size_t)blockIdx.x * 256 + threadIdx.x;
    if (i >= (size_t)NT_ * D_) return;
    out[i] = out[i] + b2[i & (D_-1)] + X2[i];
}

// ================= host launcher ============================================
extern "C" void kernel_launch(void* const* d_in, const int* in_sizes, int n_in,
                              void* d_out, int out_size)
{
    (void)in_sizes; (void)n_in; (void)out_size;
    const float* X      = (const float*)d_in[0];
    const float* Wq     = (const float*)d_in[1];
    const float* Wk     = (const float*)d_in[2];
    const float* Wv     = (const float*)d_in[3];
    const float* W_G    = (const float*)d_in[4];
    const float* W_O    = (const float*)d_in[5];
    const float* gn_w   = (const float*)d_in[6];
    const float* gn_b   = (const float*)d_in[7];
    const float* ln1_w  = (const float*)d_in[8];
    const float* ln1_b  = (const float*)d_in[9];
    const float* ln2_w  = (const float*)d_in[10];
    const float* ln2_b  = (const float*)d_in[11];
    const float* ffn_w1 = (const float*)d_in[12];
    const float* ffn_b1 = (const float*)d_in[13];
    const float* ffn_w2 = (const float*)d_in[14];
    const float* ffn_b2 = (const float*)d_in[15];
    float* out = (float*)d_out;

    float *Qf,*Kf,*Vf,*Gf,*Y,*X2,*xpt;
    bf16 *Xnh,*Xnl,*WqTh,*WqTl,*WkTh,*WkTl,*WvTh,*WvTl,*WGTh,*WGTl,*WOTh,*WOTl;
    bf16 *W1Th,*W1Tl,*W2Th,*W2Tl,*Qh,*Ql,*Kh,*Kl,*Vth,*Vtl,*Sch,*Scl,*Gh,*Gl,*h1h,*h1l;
    cudaGetSymbolAddress((void**)&Qf,  d_Qf);   cudaGetSymbolAddress((void**)&Kf,  d_Kf);
    cudaGetSymbolAddress((void**)&Vf,  d_Vf);   cudaGetSymbolAddress((void**)&Gf,  d_Gf);
    cudaGetSymbolAddress((void**)&Y,   d_Y);    cudaGetSymbolAddress((void**)&X2,  d_X2);
    cudaGetSymbolAddress((void**)&xpt, d_xpt);
    cudaGetSymbolAddress((void**)&Xnh, d_Xnh);  cudaGetSymbolAddress((void**)&Xnl, d_Xnl);
    cudaGetSymbolAddress((void**)&WqTh,d_WqTh); cudaGetSymbolAddress((void**)&WqTl,d_WqTl);
    cudaGetSymbolAddress((void**)&WkTh,d_WkTh); cudaGetSymbolAddress((void**)&WkTl,d_WkTl);
    cudaGetSymbolAddress((void**)&WvTh,d_WvTh); cudaGetSymbolAddress((void**)&WvTl,d_WvTl);
    cudaGetSymbolAddress((void**)&WGTh,d_WGTh); cudaGetSymbolAddress((void**)&WGTl,d_WGTl);
    cudaGetSymbolAddress((void**)&WOTh,d_WOTh); cudaGetSymbolAddress((void**)&WOTl,d_WOTl);
    cudaGetSymbolAddress((void**)&W1Th,d_W1Th); cudaGetSymbolAddress((void**)&W1Tl,d_W1Tl);
    cudaGetSymbolAddress((void**)&W2Th,d_W2Th); cudaGetSymbolAddress((void**)&W2Tl,d_W2Tl);
    cudaGetSymbolAddress((void**)&Qh,  d_Qh);   cudaGetSymbolAddress((void**)&Ql,  d_Ql);
    cudaGetSymbolAddress((void**)&Kh,  d_Kh);   cudaGetSymbolAddress((void**)&Kl,  d_Kl);
    cudaGetSymbolAddress((void**)&Vth, d_Vth);  cudaGetSymbolAddress((void**)&Vtl, d_Vtl);
    cudaGetSymbolAddress((void**)&Sch, d_Sch);  cudaGetSymbolAddress((void**)&Scl, d_Scl);
    cudaGetSymbolAddress((void**)&Gh,  d_Gh);   cudaGetSymbolAddress((void**)&Gl,  d_Gl);
    cudaGetSymbolAddress((void**)&h1h, d_h1h);  cudaGetSymbolAddress((void**)&h1l, d_h1l);

    cudaFuncSetAttribute(tcgemm, cudaFuncAttributeMaxDynamicSharedMemorySize, SMEM_TC);
    dim3 tb(32, 8);

    // weight transpose + split
    wsplit_t<<<dim3(D_/32,  DK_/32,  H_), tb>>>(Wq,     WqTh, WqTl, D_,  DK_);
    wsplit_t<<<dim3(D_/32,  DK_/32,  H_), tb>>>(Wk,     WkTh, WkTl, D_,  DK_);
    wsplit_t<<<dim3(D_/32,  DV_/32,  H_), tb>>>(Wv,     WvTh, WvTl, D_,  DV_);
    wsplit_t<<<dim3(D_/32,  VD_/32,  1),  tb>>>(W_G,    WGTh, WGTl, D_,  VD_);
    wsplit_t<<<dim3(VD_/32, D_/32,   1),  tb>>>(W_O,    WOTh, WOTl, VD_, D_);
    wsplit_t<<<dim3(D_/32,  FFN_/32, 1),  tb>>>(ffn_w1, W1Th, W1Tl, D_,  FFN_);
    wsplit_t<<<dim3(FFN_/32, D_/32,  1),  tb>>>(ffn_w2, W2Th, W2Tl, FFN_, D_);

    // ln1
    layernorm_split<<<NT_, 256>>>(X, ln1_w, ln1_b, Xnh, Xnl);

    // projections (fp32 outputs)
    tcgemm<<<dim3(1,16,BH_), NTHREADS, SMEM_TC>>>(Xnh, Xnl, WqTh, WqTl, Qf, nullptr,
        nullptr, DK_, D_, (long long)S_*D_, (long long)DK_*D_, (long long)S_*DK_, H_, H_, 0);
    tcgemm<<<dim3(1,16,BH_), NTHREADS, SMEM_TC>>>(Xnh, Xnl, WkTh, WkTl, Kf, nullptr,
        nullptr, DK_, D_, (long long)S_*D_, (long long)DK_*D_, (long long)S_*DK_, H_, H_, 0);
    tcgemm<<<dim3(2,16,BH_), NTHREADS, SMEM_TC>>>(Xnh, Xnl, WvTh, WvTl, Vf, nullptr,
        nullptr, DV_, D_, (long long)S_*D_, (long long)DV_*D_, (long long)S_*DV_, H_, H_, 0);
    tcgemm<<<dim3(16,32,1), NTHREADS, SMEM_TC>>>(Xnh, Xnl, WGTh, WGTl, Gf, nullptr,
        nullptr, VD_, D_, 0, 0, 0, 1, 1, 0);

    // xpos rotary -> split Q/K; V transpose+split
    xpos_table_k<<<(S_*64+255)/256, 256>>>(xpt);
    xpos_split<<<(BH_*S_*64)/256, 256>>>(Qf, Kf, xpt, Qh, Ql, Kh, Kl);
    wsplit_t<<<dim3(S_/32, DV_/32, BH_), tb>>>(Vf, Vth, Vtl, S_, DV_);

    // scores = Q K^T (fused causal decay, split bf16 out)
    tcgemm<<<dim3(16,16,BH_), NTHREADS, SMEM_TC>>>(Qh, Ql, Kh, Kl, Sch, Scl,
        nullptr, S_, DK_, (long long)S_*DK_, (long long)S_*DK_, (long long)S_*S_, 1, BH_, 1);
    // Y = Sc V  (K-limited)
    tcgemm<<<dim3(2,16,BH_), NTHREADS, SMEM_TC>>>(Sch, Scl, Vth, Vtl, Y, nullptr,
        nullptr, DV_, S_, (long long)S_*S_, (long long)DV_*S_, (long long)S_*DV_, 1, BH_, 2);

    // groupnorm + gate -> split
    gnorm_gate_split<<<B_*S_*H_, 256>>>(Y, Gf, gn_w, gn_b, Gh, Gl);

    // output projection + residual
    tcgemm<<<dim3(8,32,1), NTHREADS, SMEM_TC>>>(Gh, Gl, WOTh, WOTl, X2, nullptr,
        nullptr, D_, VD_, 0, 0, 0, 1, 1, 0);
    add_k<<<(NT_*D_)/256, 256>>>(X2, X, (size_t)NT_*D_);

    // ln2 + FFN
    layernorm_split<<<NT_, 256>>>(X2, ln2_w, ln2_b, Xnh, Xnl);
    tcgemm<<<dim3(32,32,1), NTHREADS, SMEM_TC>>>(Xnh, Xnl, W1Th, W1Tl, h1h, h1l,
        ffn_b1, FFN_, D_, 0, 0, 0, 1, 1, 3);
    tcgemm<<<dim3(8,32,1), NTHREADS, SMEM_TC>>>(h1h, h1l, W2Th, W2Tl, out, nullptr,
        nullptr, D_, FFN_, 0, 0, 0, 1, 1, 0);
    final_k<<<(NT_*D_)/256, 256>>>(out, ffn_b2, X2);
}

// round 9
// speedup vs baseline: 6.6473x; 2.1687x over previous
#include <cuda_runtime.h>
#include <cuda_fp16.h>
#include <math.h>

#define B_   2
#define S_   2048
#define D_   1024
#define H_   8
#define FFN_ 4096
#define DK_  128
#define VD_  2048
#define DV_  256
#define NT_  (B_*S_)
#define BH_  (B_*H_)

#define KC       32
#define TSTRIDE  80
#define TILE_B   (128*TSTRIDE)      // 10240 B region (8 KB payload)
#define STAGE_B  (2*TILE_B)         // 20480: A, B
#define NSTAGE   3
#define SMEM_TC  (NSTAGE*STAGE_B)   // 61440
#define NTHREADS 256

typedef __half f16;

// fp32 scratch
__device__ float d_Qf [BH_*S_*DK_];
__device__ float d_Kf [BH_*S_*DK_];
__device__ float d_Vf [BH_*S_*DV_];
__device__ float d_Gf [NT_*VD_];
__device__ float d_Y  [BH_*S_*DV_];
__device__ float d_X2 [NT_*D_];
__device__ float d_xpt[S_*64*4];
// fp16 operand buffers
__device__ f16 d_Xn16[NT_*D_];
__device__ f16 d_WqT16[H_*DK_*D_];
__device__ f16 d_WkT16[H_*DK_*D_];
__device__ f16 d_WvT16[H_*DV_*D_];
__device__ f16 d_WGT16[VD_*D_];
__device__ f16 d_WOT16[D_*VD_];
__device__ f16 d_W1T16[(size_t)D_*FFN_];
__device__ f16 d_W2T16[(size_t)D_*FFN_];
__device__ f16 d_Q16[BH_*S_*DK_];
__device__ f16 d_K16[BH_*S_*DK_];
__device__ f16 d_Vt16[BH_*DV_*S_];
__device__ f16 d_Sc16[(size_t)BH_*S_*S_];
__device__ f16 d_G16[NT_*VD_];
__device__ f16 d_h116[(size_t)NT_*FFN_];

__device__ __forceinline__ unsigned smem_u32(const void* p) {
    unsigned a;
    asm("{ .reg .u64 t; cvta.to.shared.u64 t, %1; cvt.u32.u64 %0, t; }"
        : "=r"(a) : "l"(p));
    return a;
}
__device__ __forceinline__ unsigned pack2h(float a, float b) {
    unsigned r;
    asm("cvt.rn.f16x2.f32 %0, %1, %2;" : "=r"(r) : "f"(b), "f"(a));
    return r;   // low 16 = a
}
__device__ __forceinline__ void ldm_x4(unsigned* d, unsigned addr) {
    asm volatile("ldmatrix.sync.aligned.m8n8.x4.shared.b16 {%0,%1,%2,%3}, [%4];"
        : "=r"(d[0]), "=r"(d[1]), "=r"(d[2]), "=r"(d[3]) : "r"(addr));
}
__device__ __forceinline__ void mma16816(float* c, const unsigned* a, const unsigned* b) {
    asm volatile("mma.sync.aligned.m16n8k16.row.col.f32.f16.f16.f32 "
        "{%0,%1,%2,%3}, {%4,%5,%6,%7}, {%8,%9}, {%0,%1,%2,%3};"
        : "+f"(c[0]), "+f"(c[1]), "+f"(c[2]), "+f"(c[3])
        : "r"(a[0]), "r"(a[1]), "r"(a[2]), "r"(a[3]), "r"(b[0]), "r"(b[1]));
}
__device__ __forceinline__ void cpa16(unsigned dst, const void* src) {
    asm volatile("cp.async.cg.shared.global [%0], [%1], 16;" :: "r"(dst), "l"(src));
}
#define CP_COMMIT() asm volatile("cp.async.commit_group;" ::: "memory")
#define CP_WAIT1()  asm volatile("cp.async.wait_group 1;" ::: "memory")

// ================= fp16 tensor-core GEMM (256 thr, 2 CTAs/SM, 3-stage) =====
// C[z] = A[z/aDiv] * B[z%bMod].  A fp16 row-major [M,K]; B fp16 [N,K] (B^T).
// mode 0: fp32 out.
// mode 1: scores — causal tile skip + decay, fp16 out.
// mode 2: retV — K limited to (by+1)*128, fp32 out.
// mode 3: bias + exact GELU, fp16 out.
// mode 4: fp32 out + residual add (res[M,N]).
// mode 5: fp32 out + bias[N] + residual.
__global__ __launch_bounds__(NTHREADS, 2)
void tcgemm(const f16* __restrict__ A, const f16* __restrict__ Bm,
            void* __restrict__ Cv, const float* __restrict__ bias,
            const float* __restrict__ res,
            int N, int K, long long sA, long long sB, long long sC,
            int aDiv, int bMod, int mode)
{
    int bx = blockIdx.x, by = blockIdx.y, bz = blockIdx.z;
    if (mode == 1 && bx > by) return;

    A  += (long long)(bz / aDiv) * sA;
    Bm += (long long)(bz % bMod) * sB;

    int Kuse = (mode == 2) ? min(K, (by + 1) * 128) : K;
    int nch  = Kuse >> 5;

    extern __shared__ char smem[];
    unsigned sbase = smem_u32(smem);
    int tid = threadIdx.x, wid = tid >> 5, lane = tid & 31;

    // cp.async mapping: 2 threads per row; each thread fills 2 adjacent
    // 16B chunks: dst d / d+16, src +0 / +8 elements.
    int crow = tid >> 1, cch = (tid & 1) * 2;
    const f16* gA = A  + (long long)(by * 128 + crow) * K + cch * 8;
    const f16* gB = Bm + (long long)(bx * 128 + crow) * K + cch * 8;
    unsigned cdst = (unsigned)crow * TSTRIDE + (unsigned)cch * 16;

    int wm = (wid >> 1) * 32;     // 4 warp rows
    int wn = (wid & 1) * 64;      // 2 warp cols
    float acc[2][8][4];
    #pragma unroll
    for (int i = 0; i < 2; i++)
        #pragma unroll
        for (int j = 0; j < 8; j++)
            #pragma unroll
            for (int p = 0; p < 4; p++) acc[i][j][p] = 0.f;

    unsigned a_off = (unsigned)((lane & 15) * TSTRIDE + ((lane >> 4) << 4));
    unsigned b_off = (unsigned)(((lane & 7) + ((lane >> 4) << 3)) * TSTRIDE
                                + (((lane >> 3) & 1) << 4));

    auto prefetch = [&](int s) {
        unsigned d = sbase + (unsigned)(s % NSTAGE) * STAGE_B + cdst;
        long long ko = (long long)s * KC;
        cpa16(d,                 gA + ko);
        cpa16(d + 16,            gA + ko + 8);
        cpa16(d + TILE_B,        gB + ko);
        cpa16(d + TILE_B + 16,   gB + ko + 8);
    };

    prefetch(0); CP_COMMIT();
    if (nch > 1) prefetch(1);
    CP_COMMIT();

    for (int c = 0; c < nch; c++) {
        CP_WAIT1();
        __syncthreads();
        if (c + 2 < nch) prefetch(c + 2);
        CP_COMMIT();

        unsigned sb = sbase + (unsigned)(c % NSTAGE) * STAGE_B;
        #pragma unroll
        for (int ks = 0; ks < 2; ks++) {
            unsigned kb = (unsigned)ks * 32;
            unsigned ah[2][4], bb[4][4];
            #pragma unroll
            for (int mt = 0; mt < 2; mt++)
                ldm_x4(ah[mt], sb + (unsigned)(wm + mt*16) * TSTRIDE + a_off + kb);
            #pragma unroll
            for (int p = 0; p < 4; p++)
                ldm_x4(bb[p], sb + TILE_B + (unsigned)(wn + p*16) * TSTRIDE + b_off + kb);
            #pragma unroll
            for (int mt = 0; mt < 2; mt++)
                #pragma unroll
                for (int nt = 0; nt < 8; nt++)
                    mma16816(acc[mt][nt], ah[mt], &bb[nt>>1][(nt&1)*2]);
        }
    }

    // ---------------- epilogue ----------------
    float lg2g = 0.f;
    if (mode == 1) {
        const float l32 = -3.4657359027997265f, l512 = -6.2383246250395075f;
        float g = 1.0f - expf(l32 + (l512 - l32) * (float)(bz & (H_-1)) * (1.0f/7.0f));
        lg2g = log2f(g);
    }
    bool f16out = (mode == 1 || mode == 3);
    float* Cf = (float*)Cv + (long long)bz * (f16out ? 0 : sC);
    unsigned short* Ch = (unsigned short*)Cv + (long long)bz * (f16out ? sC : 0);

    int rbase = by * 128 + wm + (lane >> 2);
    int cbase = bx * 128 + wn + (lane & 3) * 2;
    #pragma unroll
    for (int mt = 0; mt < 2; mt++) {
        #pragma unroll
        for (int half = 0; half < 2; half++) {
            int grow = rbase + mt*16 + half*8;
            #pragma unroll
            for (int nt = 0; nt < 8; nt++) {
                float v0 = acc[mt][nt][half*2], v1 = acc[mt][nt][half*2+1];
                int gcol = cbase + nt*8;
                if (mode == 1) {
                    int d0 = grow - gcol, d1 = d0 - 1;
                    v0 = (d0 >= 0) ? v0 * exp2f((float)d0 * lg2g) : 0.f;
                    v1 = (d1 >= 0) ? v1 * exp2f((float)d1 * lg2g) : 0.f;
                } else if (mode == 3) {
                    float x0 = v0 + bias[gcol], x1 = v1 + bias[gcol+1];
                    v0 = 0.5f*x0*(1.0f + erff(x0*0.70710678118654752f));
                    v1 = 0.5f*x1*(1.0f + erff(x1*0.70710678118654752f));
                } else if (mode == 4) {
                    v0 += res[(long long)grow * N + gcol];
                    v1 += res[(long long)grow * N + gcol + 1];
                } else if (mode == 5) {
                    v0 += bias[gcol]   + res[(long long)grow * N + gcol];
                    v1 += bias[gcol+1] + res[(long long)grow * N + gcol + 1];
                }
                if (f16out) {
                    *(unsigned*)(Ch + (long long)grow * N + gcol) = pack2h(v0, v1);
                } else {
                    *(float2*)(Cf + (long long)grow * N + gcol) = make_float2(v0, v1);
                }
            }
        }
    }
}

// ================= pre/post kernels =========================================
template<int NT>
__device__ __forceinline__ float blockSum(float v) {
    __shared__ float sh[NT/32];
    int lane = threadIdx.x & 31, w = threadIdx.x >> 5;
    #pragma unroll
    for (int o = 16; o > 0; o >>= 1) v += __shfl_xor_sync(0xffffffffu, v, o);
    if (lane == 0) sh[w] = v;
    __syncthreads();
    float t = 0.f;
    #pragma unroll
    for (int i = 0; i < NT/32; i++) t += sh[i];
    __syncthreads();
    return t;
}

// transpose + fp16 convert: in [K,N] fp32 (batched) -> out [N,K] fp16
__global__ void wsplit_t(const float* __restrict__ W, f16* __restrict__ T,
                         int K, int N)
{
    __shared__ float t[32][33];
    long long zo = (long long)blockIdx.z * K * N;
    int k0 = blockIdx.x*32, n0 = blockIdx.y*32;
    int tx = threadIdx.x, ty = threadIdx.y;
    #pragma unroll
    for (int j = 0; j < 32; j += 8)
        t[ty+j][tx] = W[zo + (long long)(k0+ty+j)*N + n0+tx];
    __syncthreads();
    #pragma unroll
    for (int j = 0; j < 32; j += 8)
        T[zo + (long long)(n0+ty+j)*K + k0+tx] = __float2half(t[tx][ty+j]);
}

__global__ void layernorm_f16(const float* __restrict__ X,
                              const float* __restrict__ w, const float* __restrict__ b,
                              f16* __restrict__ o)
{
    size_t tok = blockIdx.x;
    const float* x = X + tok * D_;
    int t2 = threadIdx.x * 2;
    float2 p0 = *(const float2*)(x + t2);
    float2 p1 = *(const float2*)(x + t2 + 512);
    float s = p0.x + p0.y + p1.x + p1.y;
    float mean = blockSum<256>(s) * (1.0f / D_);
    float d0 = p0.x-mean, d1 = p0.y-mean, d2 = p1.x-mean, d3 = p1.y-mean;
    float var = blockSum<256>(d0*d0 + d1*d1 + d2*d2 + d3*d3) * (1.0f / D_);
    float inv = rsqrtf(var + 1e-5f);
    float o0 = d0*inv*w[t2]     + b[t2];
    float o1 = d1*inv*w[t2+1]   + b[t2+1];
    float o2 = d2*inv*w[t2+512] + b[t2+512];
    float o3 = d3*inv*w[t2+513] + b[t2+513];
    *(unsigned*)(o + tok*D_ + t2)       = pack2h(o0, o1);
    *(unsigned*)(o + tok*D_ + t2 + 512) = pack2h(o2, o3);
}

__global__ void xpos_table_k(float* __restrict__ tab)
{
    int idx = blockIdx.x * 256 + threadIdx.x;
    if (idx >= S_ * 64) return;
    int i = idx & 63, s = idx >> 6;
    double scl = pow((2.0*i + 51.2) / 179.2, (double)s / 512.0);
    float ang_f = (float)s * (float)pow(10000.0, -(double)i / 64.0);
    double sn = sin((double)ang_f), cs = cos((double)ang_f);
    tab[idx*4+0] = (float)(cs * scl);  tab[idx*4+1] = (float)(sn * scl);
    tab[idx*4+2] = (float)(cs / scl);  tab[idx*4+3] = (float)(sn / scl);
}

__global__ void xpos_f16(const float* __restrict__ Qf, const float* __restrict__ Kf,
                         const float* __restrict__ tab,
                         f16* __restrict__ Qo, f16* __restrict__ Ko)
{
    long long idx = (long long)blockIdx.x * 256 + threadIdx.x;
    if (idx >= (long long)BH_*S_*64) return;
    int i = (int)(idx & 63);
    long long rr = idx >> 6;
    int s = (int)(rr % S_);
    long long base = rr * 128 + 2*i;
    const float* t = tab + ((long long)s*64 + i) * 4;
    float q1 = Qf[base], q2 = Qf[base+1];
    *(unsigned*)(Qo + base) = pack2h(q1*t[0] - q2*t[1], q2*t[0] + q1*t[1]);
    float k1 = Kf[base], k2 = Kf[base+1];
    *(unsigned*)(Ko + base) = pack2h(k1*t[2] - k2*t[3], k2*t[2] + k1*t[3]);
}

__global__ void gnorm_gate_f16(const float* __restrict__ Y, const float* __restrict__ G,
                               const float* __restrict__ w, const float* __restrict__ bb,
                               f16* __restrict__ o)
{
    int h = blockIdx.x % H_, s = (blockIdx.x / H_) % S_, b = blockIdx.x / (H_*S_);
    int v = threadIdx.x;
    size_t yoff = (((size_t)(b*H_+h))*S_ + s)*DV_ + v;
    float y = Y[yoff];
    float mean = blockSum<256>(y) * (1.0f/DV_);
    float d = y - mean;
    float yn = d * rsqrtf(blockSum<256>(d*d)*(1.0f/DV_) + 1e-5f);
    int col = h*DV_ + v;
    size_t goff = ((size_t)(b*S_+s))*VD_ + col;
    float g = G[goff];
    o[goff] = __float2half((g / (1.0f + expf(-g))) * (yn * w[col] + bb[col]));
}

// ================= host launcher ============================================
extern "C" void kernel_launch(void* const* d_in, const int* in_sizes, int n_in,
                              void* d_out, int out_size)
{
    (void)in_sizes; (void)n_in; (void)out_size;
    const float* X      = (const float*)d_in[0];
    const float* Wq     = (const float*)d_in[1];
    const float* Wk     = (const float*)d_in[2];
    const float* Wv     = (const float*)d_in[3];
    const float* W_G    = (const float*)d_in[4];
    const float* W_O    = (const float*)d_in[5];
    const float* gn_w   = (const float*)d_in[6];
    const float* gn_b   = (const float*)d_in[7];
    const float* ln1_w  = (const float*)d_in[8];
    const float* ln1_b  = (const float*)d_in[9];
    const float* ln2_w  = (const float*)d_in[10];
    const float* ln2_b  = (const float*)d_in[11];
    const float* ffn_w1 = (const float*)d_in[12];
    const float* ffn_b1 = (const float*)d_in[13];
    const float* ffn_w2 = (const float*)d_in[14];
    const float* ffn_b2 = (const float*)d_in[15];
    float* out = (float*)d_out;

    float *Qf,*Kf,*Vf,*Gf,*Y,*X2,*xpt;
    f16 *Xn16,*WqT,*WkT,*WvT,*WGT,*WOT,*W1T,*W2T,*Q16,*K16,*Vt16,*Sc16,*G16,*h116;
    cudaGetSymbolAddress((void**)&Qf,  d_Qf);   cudaGetSymbolAddress((void**)&Kf,  d_Kf);
    cudaGetSymbolAddress((void**)&Vf,  d_Vf);   cudaGetSymbolAddress((void**)&Gf,  d_Gf);
    cudaGetSymbolAddress((void**)&Y,   d_Y);    cudaGetSymbolAddress((void**)&X2,  d_X2);
    cudaGetSymbolAddress((void**)&xpt, d_xpt);
    cudaGetSymbolAddress((void**)&Xn16,d_Xn16);
    cudaGetSymbolAddress((void**)&WqT, d_WqT16); cudaGetSymbolAddress((void**)&WkT, d_WkT16);
    cudaGetSymbolAddress((void**)&WvT, d_WvT16); cudaGetSymbolAddress((void**)&WGT, d_WGT16);
    cudaGetSymbolAddress((void**)&WOT, d_WOT16); cudaGetSymbolAddress((void**)&W1T, d_W1T16);
    cudaGetSymbolAddress((void**)&W2T, d_W2T16);
    cudaGetSymbolAddress((void**)&Q16, d_Q16);  cudaGetSymbolAddress((void**)&K16, d_K16);
    cudaGetSymbolAddress((void**)&Vt16,d_Vt16); cudaGetSymbolAddress((void**)&Sc16,d_Sc16);
    cudaGetSymbolAddress((void**)&G16, d_G16);  cudaGetSymbolAddress((void**)&h116,d_h116);

    cudaFuncSetAttribute(tcgemm, cudaFuncAttributeMaxDynamicSharedMemorySize, SMEM_TC);
    dim3 tb(32, 8);

    // weight transpose + fp16 convert
    wsplit_t<<<dim3(D_/32,  DK_/32,  H_), tb>>>(Wq,     WqT, D_,  DK_);
    wsplit_t<<<dim3(D_/32,  DK_/32,  H_), tb>>>(Wk,     WkT, D_,  DK_);
    wsplit_t<<<dim3(D_/32,  DV_/32,  H_), tb>>>(Wv,     WvT, D_,  DV_);
    wsplit_t<<<dim3(D_/32,  VD_/32,  1),  tb>>>(W_G,    WGT, D_,  VD_);
    wsplit_t<<<dim3(VD_/32, D_/32,   1),  tb>>>(W_O,    WOT, VD_, D_);
    wsplit_t<<<dim3(D_/32,  FFN_/32, 1),  tb>>>(ffn_w1, W1T, D_,  FFN_);
    wsplit_t<<<dim3(FFN_/32, D_/32,  1),  tb>>>(ffn_w2, W2T, FFN_, D_);

    // ln1
    layernorm_f16<<<NT_, 256>>>(X, ln1_w, ln1_b, Xn16);

    // projections (fp32 outputs)
    tcgemm<<<dim3(1,16,BH_), NTHREADS, SMEM_TC>>>(Xn16, WqT, Qf, nullptr, nullptr,
        DK_, D_, (long long)S_*D_, (long long)DK_*D_, (long long)S_*DK_, H_, H_, 0);
    tcgemm<<<dim3(1,16,BH_), NTHREADS, SMEM_TC>>>(Xn16, WkT, Kf, nullptr, nullptr,
        DK_, D_, (long long)S_*D_, (long long)DK_*D_, (long long)S_*DK_, H_, H_, 0);
    tcgemm<<<dim3(2,16,BH_), NTHREADS, SMEM_TC>>>(Xn16, WvT, Vf, nullptr, nullptr,
        DV_, D_, (long long)S_*D_, (long long)DV_*D_, (long long)S_*DV_, H_, H_, 0);
    tcgemm<<<dim3(16,32,1), NTHREADS, SMEM_TC>>>(Xn16, WGT, Gf, nullptr, nullptr,
        VD_, D_, 0, 0, 0, 1, 1, 0);

    // xpos rotary -> fp16 Q/K; V transpose -> fp16
    xpos_table_k<<<(S_*64+255)/256, 256>>>(xpt);
    xpos_f16<<<(BH_*S_*64)/256, 256>>>(Qf, Kf, xpt, Q16, K16);
    wsplit_t<<<dim3(S_/32, DV_/32, BH_), tb>>>(Vf, Vt16, S_, DV_);

    // scores = Q K^T (fused causal decay, fp16 out)
    tcgemm<<<dim3(16,16,BH_), NTHREADS, SMEM_TC>>>(Q16, K16, Sc16, nullptr, nullptr,
        S_, DK_, (long long)S_*DK_, (long long)S_*DK_, (long long)S_*S_, 1, BH_, 1);
    // Y = Sc V  (K-limited, fp32 out)
    tcgemm<<<dim3(2,16,BH_), NTHREADS, SMEM_TC>>>(Sc16, Vt16, Y, nullptr, nullptr,
        DV_, S_, (long long)S_*S_, (long long)DV_*S_, (long long)S_*DV_, 1, BH_, 2);

    // groupnorm + silu gate -> fp16
    gnorm_gate_f16<<<B_*S_*H_, 256>>>(Y, Gf, gn_w, gn_b, G16);

    // output projection + fused residual (X2 = G·W_O + X)
    tcgemm<<<dim3(8,32,1), NTHREADS, SMEM_TC>>>(G16, WOT, X2, nullptr, X,
        D_, VD_, 0, 0, 0, 1, 1, 4);

    // ln2 + FFN (bias+GELU fused; final bias+residual fused)
    layernorm_f16<<<NT_, 256>>>(X2, ln2_w, ln2_b, Xn16);
    tcgemm<<<dim3(32,32,1), NTHREADS, SMEM_TC>>>(Xn16, W1T, h116, ffn_b1, nullptr,
        FFN_, D_, 0, 0, 0, 1, 1, 3);
    tcgemm<<<dim3(8,32,1), NTHREADS, SMEM_TC>>>(h116, W2T, out, ffn_b2, X2,
        D_, FFN_, 0, 0, 0, 1, 1, 5);
}

// round 10
// speedup vs baseline: 6.6610x; 1.0021x over previous
#include <cuda_runtime.h>
#include <cuda_fp16.h>
#include <math.h>

#define B_   2
#define S_   2048
#define D_   1024
#define H_   8
#define FFN_ 4096
#define DK_  128
#define VD_  2048
#define DV_  256
#define NT_  (B_*S_)
#define BH_  (B_*H_)

#define KC       32
#define TSTRIDE  80
#define TILE_B   (128*TSTRIDE)      // 10240 B region (8 KB payload)
#define STAGE_B  (2*TILE_B)         // 20480: A, B
#define NSTAGE   3
#define SMEM_TC  (NSTAGE*STAGE_B)   // 61440
#define NTHREADS 256

typedef __half f16;

// fp32 scratch
__device__ float d_Y  [BH_*S_*DV_];
__device__ float d_X2 [NT_*D_];
__device__ float d_xpt[S_*64*4];
// fp16 operand buffers
__device__ f16 d_Xn16[NT_*D_];
__device__ f16 d_WqT16[H_*DK_*D_];
__device__ f16 d_WkT16[H_*DK_*D_];
__device__ f16 d_WvT16[H_*DV_*D_];
__device__ f16 d_WGT16[VD_*D_];
__device__ f16 d_WOT16[D_*VD_];
__device__ f16 d_W1T16[(size_t)D_*FFN_];
__device__ f16 d_W2T16[(size_t)D_*FFN_];
__device__ f16 d_Q16[BH_*S_*DK_];
__device__ f16 d_K16[BH_*S_*DK_];
__device__ f16 d_V16[BH_*S_*DV_];
__device__ f16 d_Vt16[BH_*DV_*S_];
__device__ f16 d_Sc16[(size_t)BH_*S_*S_];
__device__ f16 d_G16[NT_*VD_];
__device__ f16 d_h116[(size_t)NT_*FFN_];

__device__ __forceinline__ unsigned smem_u32(const void* p) {
    unsigned a;
    asm("{ .reg .u64 t; cvta.to.shared.u64 t, %1; cvt.u32.u64 %0, t; }"
        : "=r"(a) : "l"(p));
    return a;
}
__device__ __forceinline__ unsigned pack2h(float a, float b) {
    unsigned r;
    asm("cvt.rn.f16x2.f32 %0, %1, %2;" : "=r"(r) : "f"(b), "f"(a));
    return r;   // low 16 = a
}
__device__ __forceinline__ void ldm_x4(unsigned* d, unsigned addr) {
    asm volatile("ldmatrix.sync.aligned.m8n8.x4.shared.b16 {%0,%1,%2,%3}, [%4];"
        : "=r"(d[0]), "=r"(d[1]), "=r"(d[2]), "=r"(d[3]) : "r"(addr));
}
__device__ __forceinline__ void mma16816(float* c, const unsigned* a, const unsigned* b) {
    asm volatile("mma.sync.aligned.m16n8k16.row.col.f32.f16.f16.f32 "
        "{%0,%1,%2,%3}, {%4,%5,%6,%7}, {%8,%9}, {%0,%1,%2,%3};"
        : "+f"(c[0]), "+f"(c[1]), "+f"(c[2]), "+f"(c[3])
        : "r"(a[0]), "r"(a[1]), "r"(a[2]), "r"(a[3]), "r"(b[0]), "r"(b[1]));
}
__device__ __forceinline__ void cpa16(unsigned dst, const void* src) {
    asm volatile("cp.async.cg.shared.global [%0], [%1], 16;" :: "r"(dst), "l"(src));
}
#define CP_COMMIT() asm volatile("cp.async.commit_group;" ::: "memory")
#define CP_WAIT1()  asm volatile("cp.async.wait_group 1;" ::: "memory")

// ================= fp16 tensor-core GEMM (256 thr, 2 CTAs/SM, 3-stage) =====
// C[z] = A[z/aDiv] * B[z%bMod].  A fp16 row-major [M,K]; B fp16 [N,K] (B^T).
// mode 0: fp32 out.
// mode 1: scores — causal tile skip + decay, fp16 out.
// mode 2: retV — K limited to (by+1)*128, fp32 out.
// mode 3: bias + exact GELU, fp16 out.
// mode 4: fp32 out + residual add (res[M,N]).
// mode 5: fp32 out + bias[N] + residual.
// mode 6: xpos-Q rotation (res = xpt table), fp16 out.
// mode 7: xpos-K rotation (res = xpt table), fp16 out.
// mode 8: plain fp16 out.
__global__ __launch_bounds__(NTHREADS, 2)
void tcgemm(const f16* __restrict__ A, const f16* __restrict__ Bm,
            void* __restrict__ Cv, const float* __restrict__ bias,
            const float* __restrict__ res,
            int N, int K, long long sA, long long sB, long long sC,
            int aDiv, int bMod, int mode)
{
    int bx = blockIdx.x, by = blockIdx.y, bz = blockIdx.z;
    if (mode == 1 && bx > by) return;

    A  += (long long)(bz / aDiv) * sA;
    Bm += (long long)(bz % bMod) * sB;

    int Kuse = (mode == 2) ? min(K, (by + 1) * 128) : K;
    int nch  = Kuse >> 5;

    extern __shared__ char smem[];
    unsigned sbase = smem_u32(smem);
    int tid = threadIdx.x, wid = tid >> 5, lane = tid & 31;

    int crow = tid >> 1, cch = (tid & 1) * 2;
    const f16* gA = A  + (long long)(by * 128 + crow) * K + cch * 8;
    const f16* gB = Bm + (long long)(bx * 128 + crow) * K + cch * 8;
    unsigned cdst = (unsigned)crow * TSTRIDE + (unsigned)cch * 16;

    int wm = (wid >> 1) * 32;
    int wn = (wid & 1) * 64;
    float acc[2][8][4];
    #pragma unroll
    for (int i = 0; i < 2; i++)
        #pragma unroll
        for (int j = 0; j < 8; j++)
            #pragma unroll
            for (int p = 0; p < 4; p++) acc[i][j][p] = 0.f;

    unsigned a_off = (unsigned)((lane & 15) * TSTRIDE + ((lane >> 4) << 4));
    unsigned b_off = (unsigned)(((lane & 7) + ((lane >> 4) << 3)) * TSTRIDE
                                + (((lane >> 3) & 1) << 4));

    auto prefetch = [&](int s) {
        unsigned d = sbase + (unsigned)(s % NSTAGE) * STAGE_B + cdst;
        long long ko = (long long)s * KC;
        cpa16(d,                 gA + ko);
        cpa16(d + 16,            gA + ko + 8);
        cpa16(d + TILE_B,        gB + ko);
        cpa16(d + TILE_B + 16,   gB + ko + 8);
    };

    prefetch(0); CP_COMMIT();
    if (nch > 1) prefetch(1);
    CP_COMMIT();

    for (int c = 0; c < nch; c++) {
        CP_WAIT1();
        __syncthreads();
        if (c + 2 < nch) prefetch(c + 2);
        CP_COMMIT();

        unsigned sb = sbase + (unsigned)(c % NSTAGE) * STAGE_B;
        #pragma unroll
        for (int ks = 0; ks < 2; ks++) {
            unsigned kb = (unsigned)ks * 32;
            unsigned ah[2][4], bb[4][4];
            #pragma unroll
            for (int mt = 0; mt < 2; mt++)
                ldm_x4(ah[mt], sb + (unsigned)(wm + mt*16) * TSTRIDE + a_off + kb);
            #pragma unroll
            for (int p = 0; p < 4; p++)
                ldm_x4(bb[p], sb + TILE_B + (unsigned)(wn + p*16) * TSTRIDE + b_off + kb);
            #pragma unroll
            for (int mt = 0; mt < 2; mt++)
                #pragma unroll
                for (int nt = 0; nt < 8; nt++)
                    mma16816(acc[mt][nt], ah[mt], &bb[nt>>1][(nt&1)*2]);
        }
    }

    // ---------------- epilogue ----------------
    float lg2g = 0.f;
    if (mode == 1) {
        const float l32 = -3.4657359027997265f, l512 = -6.2383246250395075f;
        float g = 1.0f - expf(l32 + (l512 - l32) * (float)(bz & (H_-1)) * (1.0f/7.0f));
        lg2g = log2f(g);
    }
    bool f16out = (mode == 1 || mode == 3 || mode >= 6);
    float* Cf = (float*)Cv + (long long)bz * (f16out ? 0 : sC);
    unsigned short* Ch = (unsigned short*)Cv + (long long)bz * (f16out ? sC : 0);

    int rbase = by * 128 + wm + (lane >> 2);
    int cbase = bx * 128 + wn + (lane & 3) * 2;
    #pragma unroll
    for (int mt = 0; mt < 2; mt++) {
        #pragma unroll
        for (int half = 0; half < 2; half++) {
            int grow = rbase + mt*16 + half*8;
            #pragma unroll
            for (int nt = 0; nt < 8; nt++) {
                float v0 = acc[mt][nt][half*2], v1 = acc[mt][nt][half*2+1];
                int gcol = cbase + nt*8;
                if (mode == 1) {
                    int d0 = grow - gcol, d1 = d0 - 1;
                    v0 = (d0 >= 0) ? v0 * exp2f((float)d0 * lg2g) : 0.f;
                    v1 = (d1 >= 0) ? v1 * exp2f((float)d1 * lg2g) : 0.f;
                } else if (mode == 3) {
                    float x0 = v0 + bias[gcol], x1 = v1 + bias[gcol+1];
                    v0 = 0.5f*x0*(1.0f + erff(x0*0.70710678118654752f));
                    v1 = 0.5f*x1*(1.0f + erff(x1*0.70710678118654752f));
                } else if (mode == 4) {
                    v0 += res[(long long)grow * N + gcol];
                    v1 += res[(long long)grow * N + gcol + 1];
                } else if (mode == 5) {
                    v0 += bias[gcol]   + res[(long long)grow * N + gcol];
                    v1 += bias[gcol+1] + res[(long long)grow * N + gcol + 1];
                } else if (mode == 6 || mode == 7) {
                    // xpos rotation: (v0,v1) = cols (2i, 2i+1), s = grow % S
                    const float* t = res + ((long long)grow * 64 + (gcol >> 1)) * 4
                                   + ((mode == 7) ? 2 : 0);
                    float c_ = t[0], s_ = t[1];
                    float o0 = v0 * c_ - v1 * s_;
                    float o1 = v1 * c_ + v0 * s_;
                    v0 = o0; v1 = o1;
                }
                if (f16out) {
                    *(unsigned*)(Ch + (long long)grow * N + gcol) = pack2h(v0, v1);
                } else {
                    *(float2*)(Cf + (long long)grow * N + gcol) = make_float2(v0, v1);
                }
            }
        }
    }
}

// ================= pre/post kernels =========================================
template<int NT>
__device__ __forceinline__ float blockSum(float v) {
    __shared__ float sh[NT/32];
    int lane = threadIdx.x & 31, w = threadIdx.x >> 5;
    #pragma unroll
    for (int o = 16; o > 0; o >>= 1) v += __shfl_xor_sync(0xffffffffu, v, o);
    if (lane == 0) sh[w] = v;
    __syncthreads();
    float t = 0.f;
    #pragma unroll
    for (int i = 0; i < NT/32; i++) t += sh[i];
    __syncthreads();
    return t;
}

// transpose + fp16 convert: in [K,N] fp32 (batched) -> out [N,K] fp16
__global__ void wsplit_t(const float* __restrict__ W, f16* __restrict__ T,
                         int K, int N)
{
    __shared__ float t[32][33];
    long long zo = (long long)blockIdx.z * K * N;
    int k0 = blockIdx.x*32, n0 = blockIdx.y*32;
    int tx = threadIdx.x, ty = threadIdx.y;
    #pragma unroll
    for (int j = 0; j < 32; j += 8)
        t[ty+j][tx] = W[zo + (long long)(k0+ty+j)*N + n0+tx];
    __syncthreads();
    #pragma unroll
    for (int j = 0; j < 32; j += 8)
        T[zo + (long long)(n0+ty+j)*K + k0+tx] = __float2half(t[tx][ty+j]);
}

// fp16 -> fp16 transpose (batched): in [K,N] -> out [N,K]
__global__ void tsp16(const f16* __restrict__ In, f16* __restrict__ T,
                      int K, int N)
{
    __shared__ f16 t[32][33];
    long long zo = (long long)blockIdx.z * K * N;
    int k0 = blockIdx.x*32, n0 = blockIdx.y*32;
    int tx = threadIdx.x, ty = threadIdx.y;
    #pragma unroll
    for (int j = 0; j < 32; j += 8)
        t[ty+j][tx] = In[zo + (long long)(k0+ty+j)*N + n0+tx];
    __syncthreads();
    #pragma unroll
    for (int j = 0; j < 32; j += 8)
        T[zo + (long long)(n0+ty+j)*K + k0+tx] = t[tx][ty+j];
}

__global__ void layernorm_f16(const float* __restrict__ X,
                              const float* __restrict__ w, const float* __restrict__ b,
                              f16* __restrict__ o)
{
    size_t tok = blockIdx.x;
    const float* x = X + tok * D_;
    int t2 = threadIdx.x * 2;
    float2 p0 = *(const float2*)(x + t2);
    float2 p1 = *(const float2*)(x + t2 + 512);
    float s = p0.x + p0.y + p1.x + p1.y;
    float mean = blockSum<256>(s) * (1.0f / D_);
    float d0 = p0.x-mean, d1 = p0.y-mean, d2 = p1.x-mean, d3 = p1.y-mean;
    float var = blockSum<256>(d0*d0 + d1*d1 + d2*d2 + d3*d3) * (1.0f / D_);
    float inv = rsqrtf(var + 1e-5f);
    float o0 = d0*inv*w[t2]     + b[t2];
    float o1 = d1*inv*w[t2+1]   + b[t2+1];
    float o2 = d2*inv*w[t2+512] + b[t2+512];
    float o3 = d3*inv*w[t2+513] + b[t2+513];
    *(unsigned*)(o + tok*D_ + t2)       = pack2h(o0, o1);
    *(unsigned*)(o + tok*D_ + t2 + 512) = pack2h(o2, o3);
}

__global__ void xpos_table_k(float* __restrict__ tab)
{
    int idx = blockIdx.x * 256 + threadIdx.x;
    if (idx >= S_ * 64) return;
    int i = idx & 63, s = idx >> 6;
    double scl = pow((2.0*i + 51.2) / 179.2, (double)s / 512.0);
    float ang_f = (float)s * (float)pow(10000.0, -(double)i / 64.0);
    double sn = sin((double)ang_f), cs = cos((double)ang_f);
    tab[idx*4+0] = (float)(cs * scl);  tab[idx*4+1] = (float)(sn * scl);
    tab[idx*4+2] = (float)(cs / scl);  tab[idx*4+3] = (float)(sn / scl);
}

__global__ void gnorm_gate_f16(const float* __restrict__ Y, const f16* __restrict__ G,
                               const float* __restrict__ w, const float* __restrict__ bb,
                               f16* __restrict__ o)
{
    int h = blockIdx.x % H_, s = (blockIdx.x / H_) % S_, b = blockIdx.x / (H_*S_);
    int v = threadIdx.x;
    size_t yoff = (((size_t)(b*H_+h))*S_ + s)*DV_ + v;
    float y = Y[yoff];
    float mean = blockSum<256>(y) * (1.0f/DV_);
    float d = y - mean;
    float yn = d * rsqrtf(blockSum<256>(d*d)*(1.0f/DV_) + 1e-5f);
    int col = h*DV_ + v;
    size_t goff = ((size_t)(b*S_+s))*VD_ + col;
    float g = __half2float(G[goff]);
    o[goff] = __float2half((g / (1.0f + expf(-g))) * (yn * w[col] + bb[col]));
}

// ================= host launcher ============================================
extern "C" void kernel_launch(void* const* d_in, const int* in_sizes, int n_in,
                              void* d_out, int out_size)
{
    (void)in_sizes; (void)n_in; (void)out_size;
    const float* X      = (const float*)d_in[0];
    const float* Wq     = (const float*)d_in[1];
    const float* Wk     = (const float*)d_in[2];
    const float* Wv     = (const float*)d_in[3];
    const float* W_G    = (const float*)d_in[4];
    const float* W_O    = (const float*)d_in[5];
    const float* gn_w   = (const float*)d_in[6];
    const float* gn_b   = (const float*)d_in[7];
    const float* ln1_w  = (const float*)d_in[8];
    const float* ln1_b  = (const float*)d_in[9];
    const float* ln2_w  = (const float*)d_in[10];
    const float* ln2_b  = (const float*)d_in[11];
    const float* ffn_w1 = (const float*)d_in[12];
    const float* ffn_b1 = (const float*)d_in[13];
    const float* ffn_w2 = (const float*)d_in[14];
    const float* ffn_b2 = (const float*)d_in[15];
    float* out = (float*)d_out;

    float *Y,*X2,*xpt;
    f16 *Xn16,*WqT,*WkT,*WvT,*WGT,*WOT,*W1T,*W2T,*Q16,*K16,*V16,*Vt16,*Sc16,*G16,*h116;
    cudaGetSymbolAddress((void**)&Y,   d_Y);    cudaGetSymbolAddress((void**)&X2,  d_X2);
    cudaGetSymbolAddress((void**)&xpt, d_xpt);
    cudaGetSymbolAddress((void**)&Xn16,d_Xn16);
    cudaGetSymbolAddress((void**)&WqT, d_WqT16); cudaGetSymbolAddress((void**)&WkT, d_WkT16);
    cudaGetSymbolAddress((void**)&WvT, d_WvT16); cudaGetSymbolAddress((void**)&WGT, d_WGT16);
    cudaGetSymbolAddress((void**)&WOT, d_WOT16); cudaGetSymbolAddress((void**)&W1T, d_W1T16);
    cudaGetSymbolAddress((void**)&W2T, d_W2T16);
    cudaGetSymbolAddress((void**)&Q16, d_Q16);  cudaGetSymbolAddress((void**)&K16, d_K16);
    cudaGetSymbolAddress((void**)&V16, d_V16);  cudaGetSymbolAddress((void**)&Vt16,d_Vt16);
    cudaGetSymbolAddress((void**)&Sc16,d_Sc16);
    cudaGetSymbolAddress((void**)&G16, d_G16);  cudaGetSymbolAddress((void**)&h116,d_h116);

    cudaFuncSetAttribute(tcgemm, cudaFuncAttributeMaxDynamicSharedMemorySize, SMEM_TC);
    dim3 tb(32, 8);

    // weight transpose + fp16 convert; xpos table
    wsplit_t<<<dim3(D_/32,  DK_/32,  H_), tb>>>(Wq,     WqT, D_,  DK_);
    wsplit_t<<<dim3(D_/32,  DK_/32,  H_), tb>>>(Wk,     WkT, D_,  DK_);
    wsplit_t<<<dim3(D_/32,  DV_/32,  H_), tb>>>(Wv,     WvT, D_,  DV_);
    wsplit_t<<<dim3(D_/32,  VD_/32,  1),  tb>>>(W_G,    WGT, D_,  VD_);
    wsplit_t<<<dim3(VD_/32, D_/32,   1),  tb>>>(W_O,    WOT, VD_, D_);
    wsplit_t<<<dim3(D_/32,  FFN_/32, 1),  tb>>>(ffn_w1, W1T, D_,  FFN_);
    wsplit_t<<<dim3(FFN_/32, D_/32,  1),  tb>>>(ffn_w2, W2T, FFN_, D_);
    xpos_table_k<<<(S_*64+255)/256, 256>>>(xpt);

    // ln1
    layernorm_f16<<<NT_, 256>>>(X, ln1_w, ln1_b, Xn16);

    // projections: Q/K with fused xpos (fp16 out), V fp16, G fp16
    tcgemm<<<dim3(1,16,BH_), NTHREADS, SMEM_TC>>>(Xn16, WqT, Q16, nullptr, xpt,
        DK_, D_, (long long)S_*D_, (long long)DK_*D_, (long long)S_*DK_, H_, H_, 6);
    tcgemm<<<dim3(1,16,BH_), NTHREADS, SMEM_TC>>>(Xn16, WkT, K16, nullptr, xpt,
        DK_, D_, (long long)S_*D_, (long long)DK_*D_, (long long)S_*DK_, H_, H_, 7);
    tcgemm<<<dim3(2,16,BH_), NTHREADS, SMEM_TC>>>(Xn16, WvT, V16, nullptr, nullptr,
        DV_, D_, (long long)S_*D_, (long long)DV_*D_, (long long)S_*DV_, H_, H_, 8);
    tcgemm<<<dim3(16,32,1), NTHREADS, SMEM_TC>>>(Xn16, WGT, G16, nullptr, nullptr,
        VD_, D_, 0, 0, 0, 1, 1, 8);

    // V transpose fp16
    tsp16<<<dim3(S_/32, DV_/32, BH_), tb>>>(V16, Vt16, S_, DV_);

    // scores = Q K^T (fused causal decay, fp16 out)
    tcgemm<<<dim3(16,16,BH_), NTHREADS, SMEM_TC>>>(Q16, K16, Sc16, nullptr, nullptr,
        S_, DK_, (long long)S_*DK_, (long long)S_*DK_, (long long)S_*S_, 1, BH_, 1);
    // Y = Sc V  (K-limited, fp32 out)
    tcgemm<<<dim3(2,16,BH_), NTHREADS, SMEM_TC>>>(Sc16, Vt16, Y, nullptr, nullptr,
        DV_, S_, (long long)S_*S_, (long long)DV_*S_, (long long)S_*DV_, 1, BH_, 2);

    // groupnorm + silu gate -> fp16
    gnorm_gate_f16<<<B_*S_*H_, 256>>>(Y, G16, gn_w, gn_b, G16);

    // output projection + fused residual (X2 = G·W_O + X)
    tcgemm<<<dim3(8,32,1), NTHREADS, SMEM_TC>>>(G16, WOT, X2, nullptr, X,
        D_, VD_, 0, 0, 0, 1, 1, 4);

    // ln2 + FFN (bias+GELU fused; final bias+residual fused)
    layernorm_f16<<<NT_, 256>>>(X2, ln2_w, ln2_b, Xn16);
    tcgemm<<<dim3(32,32,1), NTHREADS, SMEM_TC>>>(Xn16, W1T, h116, ffn_b1, nullptr,
        FFN_, D_, 0, 0, 0, 1, 1, 3);
    tcgemm<<<dim3(8,32,1), NTHREADS, SMEM_TC>>>(h116, W2T, out, ffn_b2, X2,
        D_, FFN_, 0, 0, 0, 1, 1, 5);
}